// round 12
// baseline (speedup 1.0000x reference)
#include <cuda_runtime.h>
#include <cuda_fp16.h>
#include <cmath>
#include <cstdint>

#define T_ 4
#define B_ 8
#define C_ 512
#define N_ 1024
#define TB 32
#define CN (C_*N_)          // 524288
#define TBCN (TB*CN)        // 16777216
#define PER_T (B_*CN)       // 4194304

// Scratch (static device globals — no runtime allocation)
__device__ __half gh_q[TBCN];        // q spikes fp16 (binary, exact)
__device__ __half gh_k[TBCN];
__device__ __half gh_v[TBCN];
__device__ __half gh_a[TBCN];        // attn spikes
__device__ __half g_kvh[TB*8*64*64]; // kv^T [tbh][e][d], counts <=1024, fp16-exact
__device__ __half g_whi[4*C_*C_];    // W hi (x 2^11) for q,k,v,p
__device__ __half g_wlo[4*C_*C_];    // W lo
__device__ __half g_xhi[TBCN];       // x hi fp16 [z][c][n]
__device__ __half g_xlo[TBCN];       // x lo

#define WSCALE     2048.0f
#define WSCALE_INV 4.8828125e-4f     // 2^-11, exact

// Vst: 128 x 129 fp32 (stride 129 spreads banks; fits 2 CTAs/SM with 48KB panels)
#define VST_STRIDE 129
#define PANELS_BYTES 49152           // 3 stages x 16KB

// ============================================================================
// helpers
// ============================================================================
__device__ __forceinline__ uint32_t smem_u32(const void* p) {
    uint32_t a;
    asm("{ .reg .u64 t; cvta.to.shared.u64 t, %1; cvt.u32.u64 %0, t; }" : "=r"(a) : "l"(p));
    return a;
}
__device__ __forceinline__ uint32_t packh(__half a, __half b) {
    __half2 h = __halves2half2(a, b);
    return *(uint32_t*)&h;
}
__device__ __forceinline__ void ldmx4(uint32_t* r, uint32_t addr) {
    asm volatile("ldmatrix.sync.aligned.m8n8.x4.shared.b16 {%0,%1,%2,%3}, [%4];"
                 : "=r"(r[0]), "=r"(r[1]), "=r"(r[2]), "=r"(r[3]) : "r"(addr));
}
__device__ __forceinline__ void ldmx4t(uint32_t* r, uint32_t addr) {
    asm volatile("ldmatrix.sync.aligned.m8n8.x4.trans.shared.b16 {%0,%1,%2,%3}, [%4];"
                 : "=r"(r[0]), "=r"(r[1]), "=r"(r[2]), "=r"(r[3]) : "r"(addr));
}
__device__ __forceinline__ void mma16(float* c, const uint32_t* a, const uint32_t* b) {
    asm volatile("mma.sync.aligned.m16n8k16.row.col.f32.f16.f16.f32 "
                 "{%0,%1,%2,%3}, {%4,%5,%6,%7}, {%8,%9}, {%0,%1,%2,%3};"
                 : "+f"(c[0]), "+f"(c[1]), "+f"(c[2]), "+f"(c[3])
                 : "r"(a[0]), "r"(a[1]), "r"(a[2]), "r"(a[3]), "r"(b[0]), "r"(b[1]));
}
__device__ __forceinline__ void cp16(uint32_t dst, const void* src) {
    asm volatile("cp.async.cg.shared.global [%0], [%1], 16;" :: "r"(dst), "l"(src) : "memory");
}
#define CP_COMMIT() asm volatile("cp.async.commit_group;" ::: "memory")
#define CP_WAIT0()  asm volatile("cp.async.wait_group 0;" ::: "memory")
#define CP_WAIT1()  asm volatile("cp.async.wait_group 1;" ::: "memory")

// exact reference LIF step: v' = v + (x - v)*0.5 ; spike >= thr ; hard reset
__device__ __forceinline__ float lif_step(float& vv, float x, float thr) {
    vv = __fadd_rn(vv, __fmul_rn(__fsub_rn(x, vv), 0.5f));
    float s = (vv >= thr) ? 1.0f : 0.0f;
    if (vv >= thr) vv = 0.0f;
    return s;
}

// ============================================================================
// Pre-split kernels (arithmetic identical to the proven inline splits)
// ============================================================================
__global__ void split_w(const float* __restrict__ w0, const float* __restrict__ w1,
                        const float* __restrict__ w2, const float* __restrict__ w3)
{
    int i = blockIdx.x * 256 + threadIdx.x;      // 0 .. 4*262144-1
    int which = i >> 18, off = i & 262143;
    const float* w = (which == 0) ? w0 : (which == 1) ? w1 : (which == 2) ? w2 : w3;
    float s = w[off] * WSCALE;
    __half hi = __float2half_rn(s);
    __half lo = __float2half_rn(s - __half2float(hi));
    g_whi[i] = hi;
    g_wlo[i] = lo;
}

__global__ void split_x(const float* __restrict__ x)
{
    size_t i4 = (size_t)blockIdx.x * 256 + threadIdx.x;   // 0 .. TBCN/4-1
    float4 v = *(const float4*)(x + i4 * 4);
    __half h0 = __float2half_rn(v.x), h1 = __float2half_rn(v.y);
    __half h2 = __float2half_rn(v.z), h3 = __float2half_rn(v.w);
    __half l0 = __float2half_rn(v.x - __half2float(h0));
    __half l1 = __float2half_rn(v.y - __half2float(h1));
    __half l2 = __float2half_rn(v.z - __half2float(h2));
    __half l3 = __float2half_rn(v.w - __half2float(h3));
    *(uint2*)(g_xhi + i4 * 4) = make_uint2(packh(h0, h1), packh(h2, h3));
    *(uint2*)(g_xlo + i4 * 4) = make_uint2(packh(l0, l1), packh(l2, l3));
}

// ============================================================================
// Core GEMM + BN (+ optional multi-step LIF) with 3-stage cp.async pipeline.
// All operands fp16 in gmem. M128 x N128, 8 warps of 64x32, K-chunk 16.
// Stage st occupies smbuf + st*16384: Ah @0, Al @4096, Bh @8192, Bl @12288.
// NSPLIT=3: (Whi+Wlo) x Bhi + Whi x Blo.  NSPLIT=2: (Whi+Wlo) x Bhi.
// NT=4 + DO_LIF: t-loop with LIF state in SMEM.
// ============================================================================
template<int NSPLIT, typename TOUT, bool DO_LIF, int NT>
__device__ __forceinline__ void gemm_body(
    const __half* __restrict__ Whi, const __half* __restrict__ Wlo,
    const __half* __restrict__ Bhi, const __half* __restrict__ Blo,
    TOUT* __restrict__ OUT,
    const float* __restrict__ gamma, const float* __restrict__ beta,
    const float* __restrict__ bias, float inv, float thr,
    char* smbuf, int b, int m0, int n0)
{
    const uint32_t sbase = smem_u32(smbuf);
    float* Vst = (float*)(smbuf + PANELS_BYTES);

    const int tid  = threadIdx.x;
    const int lane = tid & 31;
    const int wid  = tid >> 5;
    const int wm   = (wid >> 2) * 64;
    const int wn   = (wid & 3) * 32;

    if (DO_LIF) {
        for (int i = tid; i < 128 * VST_STRIDE; i += 256) Vst[i] = 0.0f;
    }

    // cp.async loader indices
    const int mA  = tid >> 1;            // 0..127
    const int kh8 = tid & 1;             // k-group of 8
    const __half* WhiRow = Whi + (size_t)(m0 + mA) * C_ + kh8 * 8;
    const __half* WloRow = Wlo + (size_t)(m0 + mA) * C_ + kh8 * 8;
    const uint32_t abyte = (uint32_t)((mA * 2 + (kh8 ^ ((mA >> 2) & 1))) * 16);
    const int kB  = tid >> 4;            // 0..15
    const int seg = tid & 15;
    const uint32_t bbyte = (uint32_t)(kB * 256 + ((seg ^ (kB & 7))) * 16);

    // ldmatrix lane offsets (R9-proven)
    const int mrel = (lane & 7) | (((lane >> 3) & 1) << 3);
    const int hA   = (lane >> 4) & 1;
    uint32_t offA[4];
#pragma unroll
    for (int mt = 0; mt < 4; mt++) {
        int m = wm + mt * 16 + mrel;
        offA[mt] = (uint32_t)((m * 2 + (hA ^ ((m >> 2) & 1))) * 16);
    }
    const int krel = (lane & 7) | (((lane >> 3) & 1) << 3);
    const int nrel = ((lane >> 4) & 1) * 8;
    uint32_t offB[2];
#pragma unroll
    for (int p = 0; p < 2; p++) {
        int n = wn + p * 16 + nrel;
        offB[p] = (uint32_t)(krel * 256 + (((n >> 3) ^ (krel & 7))) * 16);
    }

    if (DO_LIF) __syncthreads();

#pragma unroll 1
    for (int t = 0; t < NT; t++) {
        const size_t zoff = (size_t)(NT == 4 ? (t * 8 + b) : b) * CN;
        const __half* BhiBase = Bhi + zoff + (size_t)kB * N_ + n0 + seg * 8;
        const __half* BloBase = (NSPLIT >= 3) ? (Blo + zoff + (size_t)kB * N_ + n0 + seg * 8)
                                              : (const __half*)nullptr;

        float acc[4][4][4];
#pragma unroll
        for (int i = 0; i < 4; i++)
#pragma unroll
            for (int j = 0; j < 4; j++)
#pragma unroll
                for (int e = 0; e < 4; e++) acc[i][j][e] = 0.0f;

        auto ISSUE = [&](int ch) {
            const uint32_t st = (uint32_t)(ch % 3) * 16384u;
            const int kb = ch * 16;
            cp16(sbase + st + abyte,         WhiRow + kb);
            cp16(sbase + st + 4096 + abyte,  WloRow + kb);
            cp16(sbase + st + 8192 + bbyte,  BhiBase + (size_t)kb * N_);
            if (NSPLIT >= 3)
                cp16(sbase + st + 12288 + bbyte, BloBase + (size_t)kb * N_);
            CP_COMMIT();
        };

        auto COMP = [&](int ch) {
            const uint32_t st = (uint32_t)(ch % 3) * 16384u;
            const uint32_t aHi = sbase + st;
            const uint32_t aLo = sbase + st + 4096;
            const uint32_t bHi = sbase + st + 8192;
            const uint32_t bLo = sbase + st + 12288;

            uint32_t ah[4][4], bh[4][2];
#pragma unroll
            for (int mt = 0; mt < 4; mt++) ldmx4(ah[mt], aHi + offA[mt]);
#pragma unroll
            for (int p = 0; p < 2; p++) {
                uint32_t tr[4];
                ldmx4t(tr, bHi + offB[p]);
                bh[2 * p][0] = tr[0]; bh[2 * p][1] = tr[1];
                bh[2 * p + 1][0] = tr[2]; bh[2 * p + 1][1] = tr[3];
            }
#pragma unroll
            for (int mt = 0; mt < 4; mt++)
#pragma unroll
                for (int nt = 0; nt < 4; nt++) mma16(acc[mt][nt], ah[mt], bh[nt]);
            if (NSPLIT >= 3) {
                uint32_t bl[4][2];
#pragma unroll
                for (int p = 0; p < 2; p++) {
                    uint32_t tr[4];
                    ldmx4t(tr, bLo + offB[p]);
                    bl[2 * p][0] = tr[0]; bl[2 * p][1] = tr[1];
                    bl[2 * p + 1][0] = tr[2]; bl[2 * p + 1][1] = tr[3];
                }
#pragma unroll
                for (int mt = 0; mt < 4; mt++)
#pragma unroll
                    for (int nt = 0; nt < 4; nt++) mma16(acc[mt][nt], ah[mt], bl[nt]);
            }
#pragma unroll
            for (int mt = 0; mt < 4; mt++) ldmx4(ah[mt], aLo + offA[mt]);
#pragma unroll
            for (int mt = 0; mt < 4; mt++)
#pragma unroll
                for (int nt = 0; nt < 4; nt++) mma16(acc[mt][nt], ah[mt], bh[nt]);
        };

        // 3-stage pipeline: chunk ch is waited with 2 COMP epochs of lead.
        ISSUE(0);
        ISSUE(1);
#pragma unroll 1
        for (int ch = 0; ch < 32; ch++) {
            if (ch == 31) { CP_WAIT0(); } else { CP_WAIT1(); }
            __syncthreads();                 // chunk ch visible; COMP(ch-1) retired
            if (ch < 30) ISSUE(ch + 2);      // buffer (ch+2)%3 == (ch-1)%3, retired
            COMP(ch);
        }

        // Epilogue: descale (exact 2^-11), BN (exact jax op order), optional LIF.
        {
            const int rb = m0 + wm + (lane >> 2);
            const int cb = n0 + wn + 2 * (lane & 3);
            const int rlb = wm + (lane >> 2);
            const int clb = wn + 2 * (lane & 3);
            TOUT* Oz = OUT + zoff;
#pragma unroll
            for (int mt = 0; mt < 4; mt++) {
                int r0 = rb + mt * 16, r1 = r0 + 8;
                float g0 = gamma[r0], g1 = gamma[r1];
                float e0 = beta[r0],  e1 = beta[r1];
                float b0 = bias ? bias[r0] : 0.0f;
                float b1 = bias ? bias[r1] : 0.0f;
                float* vrow0 = &Vst[(rlb + mt * 16) * VST_STRIDE + clb];
                float* vrow1 = vrow0 + 8 * VST_STRIDE;
#pragma unroll
                for (int nt = 0; nt < 4; nt++) {
                    int cc = cb + nt * 8;
                    float* c = acc[mt][nt];
                    float y0 = __fmul_rn(c[0], WSCALE_INV);
                    float y1 = __fmul_rn(c[1], WSCALE_INV);
                    float y2 = __fmul_rn(c[2], WSCALE_INV);
                    float y3 = __fmul_rn(c[3], WSCALE_INV);
                    if (bias) { y0 = __fadd_rn(y0, b0); y1 = __fadd_rn(y1, b0);
                                y2 = __fadd_rn(y2, b1); y3 = __fadd_rn(y3, b1); }
                    y0 = __fadd_rn(__fmul_rn(__fmul_rn(g0, y0), inv), e0);
                    y1 = __fadd_rn(__fmul_rn(__fmul_rn(g0, y1), inv), e0);
                    y2 = __fadd_rn(__fmul_rn(__fmul_rn(g1, y2), inv), e1);
                    y3 = __fadd_rn(__fmul_rn(__fmul_rn(g1, y3), inv), e1);
                    if (DO_LIF) {
                        float vv0 = vrow0[nt * 8],     vv1 = vrow0[nt * 8 + 1];
                        float vv2 = vrow1[nt * 8],     vv3 = vrow1[nt * 8 + 1];
                        float s0 = lif_step(vv0, y0, thr);
                        float s1 = lif_step(vv1, y1, thr);
                        float s2 = lif_step(vv2, y2, thr);
                        float s3 = lif_step(vv3, y3, thr);
                        vrow0[nt * 8] = vv0; vrow0[nt * 8 + 1] = vv1;
                        vrow1[nt * 8] = vv2; vrow1[nt * 8 + 1] = vv3;
                        if (sizeof(TOUT) == 2) {
                            *(uint32_t*)((__half*)Oz + (size_t)r0 * N_ + cc) =
                                packh(__float2half_rn(s0), __float2half_rn(s1));
                            *(uint32_t*)((__half*)Oz + (size_t)r1 * N_ + cc) =
                                packh(__float2half_rn(s2), __float2half_rn(s3));
                        } else {
                            *(float2*)((float*)Oz + (size_t)r0 * N_ + cc) = make_float2(s0, s1);
                            *(float2*)((float*)Oz + (size_t)r1 * N_ + cc) = make_float2(s2, s3);
                        }
                    } else {
                        *(float2*)((float*)Oz + (size_t)r0 * N_ + cc) = make_float2(y0, y1);
                        *(float2*)((float*)Oz + (size_t)r1 * N_ + cc) = make_float2(y2, y3);
                    }
                }
            }
        }
    }
}

// ============================================================================
// Merged q/k/v GEMM+BN+LIF: grid z = mi*8 + b (768 CTAs, one pool)
// ============================================================================
__global__ __launch_bounds__(256, 2) void gemm_lif_qkv(
    __half* __restrict__ oq, __half* __restrict__ ok, __half* __restrict__ ov,
    const float* __restrict__ qg, const float* __restrict__ qb,
    const float* __restrict__ kg, const float* __restrict__ kb,
    const float* __restrict__ vg, const float* __restrict__ vb,
    float inv)
{
    extern __shared__ char smbuf[];
    const int z  = blockIdx.z;
    const int mi = z >> 3;
    const int b  = z & 7;
    const __half* Whi = g_whi + (size_t)mi * C_ * C_;
    const __half* Wlo = g_wlo + (size_t)mi * C_ * C_;
    __half* OUT    = (mi == 0) ? oq : (mi == 1) ? ok : ov;
    const float* g = (mi == 0) ? qg : (mi == 1) ? kg : vg;
    const float* e = (mi == 0) ? qb : (mi == 1) ? kb : vb;
    gemm_body<3, __half, true, 4>(Whi, Wlo, g_xhi, g_xlo, OUT, g, e, nullptr,
                                  inv, 1.0f, smbuf, b,
                                  blockIdx.y * 128, blockIdx.x * 128);
}

// ============================================================================
// Projection GEMM fused with BN + LIF: z = 0..7 (256 CTAs = one wave).
// Binary fp16 B (exact), float spike output straight to d_out.
// ============================================================================
__global__ __launch_bounds__(256, 2) void gemm_lif_p(
    float* __restrict__ OUT,
    const float* __restrict__ gamma, const float* __restrict__ beta,
    const float* __restrict__ bias, float inv)
{
    extern __shared__ char smbuf[];
    const __half* Whi = g_whi + (size_t)3 * C_ * C_;
    const __half* Wlo = g_wlo + (size_t)3 * C_ * C_;
    gemm_body<2, float, true, 4>(Whi, Wlo, gh_a, nullptr, OUT,
                                 gamma, beta, bias, inv, 1.0f,
                                 smbuf, blockIdx.z,
                                 blockIdx.y * 128, blockIdx.x * 128);
}

// ============================================================================
// kv via tensor cores (R7-proven): kv[d][e] -> g_kvh[tbh][e][d]
// ============================================================================
__global__ __launch_bounds__(256) void kv_mma()
{
    __shared__ char sK[16384];
    __shared__ char sV[16384];

    const int tbh = blockIdx.x;
    const int tb = tbh >> 3, h = tbh & 7;
    const __half* K = gh_k + (size_t)tb * CN + (size_t)h * 64 * N_;
    const __half* V = gh_v + (size_t)tb * CN + (size_t)h * 64 * N_;

    const int tid = threadIdx.x;
    const int lane = tid & 31;
    const int w = tid >> 5;
    const int mt = (w & 3) * 16;
    const int nh = (w >> 2) * 32;

    const uint32_t skb = smem_u32(sK);
    const uint32_t svb = smem_u32(sV);

    float acc[4][4];
#pragma unroll
    for (int i = 0; i < 4; i++)
#pragma unroll
        for (int j = 0; j < 4; j++) acc[i][j] = 0.0f;

    const __half* src = (tid < 128) ? K : V;
    char* dstp = (tid < 128) ? sK : sV;
    const int lt = tid & 127;

#pragma unroll 1
    for (int c = 0; c < 8; c++) {
        __syncthreads();
#pragma unroll
        for (int i = 0; i < 8; i++) {
            int idx = lt + i * 128;
            int row = idx >> 4, seg = idx & 15;
            int phys = seg ^ (row & 7);
            *(uint4*)(dstp + row * 256 + phys * 16) =
                *(const uint4*)(src + (size_t)row * N_ + c * 128 + seg * 8);
        }
        __syncthreads();

#pragma unroll
        for (int j = 0; j < 8; j++) {
            uint32_t a[4];
            {
                int row = mt + (lane & 7) + ((lane >> 3) & 1) * 8;
                int seg = 2 * j + (lane >> 4);
                ldmx4(a, skb + row * 256 + (seg ^ (row & 7)) * 16);
            }
#pragma unroll
            for (int p = 0; p < 2; p++) {
                uint32_t r[4];
                int row = nh + p * 16 + (lane & 7) + ((lane >> 4) & 1) * 8;
                int seg = 2 * j + ((lane >> 3) & 1);
                ldmx4(r, svb + row * 256 + (seg ^ (row & 7)) * 16);
                mma16(acc[2 * p],     a, &r[0]);
                mma16(acc[2 * p + 1], a, &r[2]);
            }
        }
    }

    __half* out = g_kvh + (size_t)tbh * 4096;
    const int d0 = mt + (lane >> 2);
    const int eb = nh + 2 * (lane & 3);
#pragma unroll
    for (int nt = 0; nt < 4; nt++) {
        int e = eb + nt * 8;
        out[(size_t)e * 64 + d0]           = __float2half_rn(acc[nt][0]);
        out[(size_t)(e + 1) * 64 + d0]     = __float2half_rn(acc[nt][1]);
        out[(size_t)e * 64 + d0 + 8]       = __float2half_rn(acc[nt][2]);
        out[(size_t)(e + 1) * 64 + d0 + 8] = __float2half_rn(acc[nt][3]);
    }
}

// ============================================================================
// av via tensor cores + fused attn-LIF (R7-proven)
// ============================================================================
__global__ __launch_bounds__(256, 2) void av_lif_mma()
{
    __shared__ char sA[8192];
    __shared__ char sQ[32768];

    const int bh = blockIdx.y;
    const int b = bh >> 3, h = bh & 7;
    const int n0 = blockIdx.x * 128;

    const int tid = threadIdx.x;
    const int lane = tid & 31;
    const int w = tid >> 5;

    const uint32_t sab = smem_u32(sA);
    const uint32_t sqb = smem_u32(sQ);

    const int mrel = (lane & 7) + ((lane >> 3) & 1) * 8;
    const int hA = (lane >> 4) & 1;
    const int krel = (lane & 7) | (((lane >> 3) & 1) << 3);
    const int nrel = ((lane >> 4) & 1) * 8;
    const int nseg = (w * 16 + nrel) >> 3;

    float vst[4][2][4];
#pragma unroll
    for (int i = 0; i < 4; i++)
#pragma unroll
        for (int j = 0; j < 2; j++)
#pragma unroll
            for (int e = 0; e < 4; e++) vst[i][j][e] = 0.0f;

#pragma unroll 1
    for (int t = 0; t < 4; t++) {
        const int tb = t * 8 + b;
        const __half* KV = g_kvh + ((size_t)tb * 8 + h) * 4096;
        const __half* Q  = gh_q + (size_t)tb * CN + (size_t)h * 64 * N_;

        __syncthreads();
#pragma unroll
        for (int i = 0; i < 2; i++) {
            int idx = tid + i * 256;
            int e = idx >> 3, seg = idx & 7;
            int phys = seg ^ (e & 7);
            *(uint4*)(sA + e * 128 + phys * 16) =
                *(const uint4*)(KV + (size_t)e * 64 + seg * 8);
        }
#pragma unroll
        for (int i = 0; i < 4; i++) {
            int idx = tid + i * 256;
            int d = idx >> 4, seg = idx & 15;
            int phys = seg ^ (d & 7);
            *(uint4*)(sQ + d * 256 + phys * 16) =
                *(const uint4*)(Q + (size_t)d * N_ + n0 + seg * 8);
        }
        __syncthreads();

        float acc[4][2][4];
#pragma unroll
        for (int i = 0; i < 4; i++)
#pragma unroll
            for (int j = 0; j < 2; j++)
#pragma unroll
                for (int e = 0; e < 4; e++) acc[i][j][e] = 0.0f;

#pragma unroll
        for (int j = 0; j < 4; j++) {
            uint32_t bq[2][2];
            {
                uint32_t tr[4];
                int kr = j * 16 + krel;
                ldmx4t(tr, sqb + kr * 256 + ((nseg ^ (kr & 7))) * 16);
                bq[0][0] = tr[0]; bq[0][1] = tr[1];
                bq[1][0] = tr[2]; bq[1][1] = tr[3];
            }
#pragma unroll
            for (int mt = 0; mt < 4; mt++) {
                uint32_t a[4];
                int row = mt * 16 + mrel;
                int seg = 2 * j + hA;
                ldmx4(a, sab + row * 128 + ((seg ^ (row & 7))) * 16);
                mma16(acc[mt][0], a, bq[0]);
                mma16(acc[mt][1], a, bq[1]);
            }
        }

        __half* A = gh_a + (size_t)tb * CN + (size_t)h * 64 * N_;
        const int cb = n0 + w * 16 + 2 * (lane & 3);
#pragma unroll
        for (int mt = 0; mt < 4; mt++) {
            int e0 = mt * 16 + (lane >> 2), e1 = e0 + 8;
#pragma unroll
            for (int nt = 0; nt < 2; nt++) {
                int cc = cb + nt * 8;
                float* c = acc[mt][nt];
                float* vv = vst[mt][nt];
                float s0 = lif_step(vv[0], __fmul_rn(c[0], 0.125f), 0.5f);
                float s1 = lif_step(vv[1], __fmul_rn(c[1], 0.125f), 0.5f);
                float s2 = lif_step(vv[2], __fmul_rn(c[2], 0.125f), 0.5f);
                float s3 = lif_step(vv[3], __fmul_rn(c[3], 0.125f), 0.5f);
                *(uint32_t*)(A + (size_t)e0 * N_ + cc) =
                    packh(__float2half_rn(s0), __float2half_rn(s1));
                *(uint32_t*)(A + (size_t)e1 * N_ + cc) =
                    packh(__float2half_rn(s2), __float2half_rn(s3));
            }
        }
    }
}

// ============================================================================
extern "C" void kernel_launch(void* const* d_in, const int* in_sizes, int n_in,
                              void* d_out, int out_size)
{
    const float* x   = (const float*)d_in[0];
    const float* Wq  = (const float*)d_in[1];
    const float* qg  = (const float*)d_in[2];
    const float* qb  = (const float*)d_in[3];
    const float* Wk  = (const float*)d_in[4];
    const float* kg  = (const float*)d_in[5];
    const float* kb  = (const float*)d_in[6];
    const float* Wv  = (const float*)d_in[7];
    const float* vg  = (const float*)d_in[8];
    const float* vb  = (const float*)d_in[9];
    const float* Wp  = (const float*)d_in[10];
    const float* bp  = (const float*)d_in[11];
    const float* pg  = (const float*)d_in[12];
    const float* pb  = (const float*)d_in[13];
    float* out = (float*)d_out;

    __half *hq, *hk, *hv;
    cudaGetSymbolAddress((void**)&hq, gh_q);
    cudaGetSymbolAddress((void**)&hk, gh_k);
    cudaGetSymbolAddress((void**)&hv, gh_v);

    float one_eps = 1.0f + 1e-5f;
    float inv = (float)(1.0 / sqrt((double)one_eps));

    const int SMEM = PANELS_BYTES + 128 * VST_STRIDE * 4;   // 49152 + 66048 = 115200
    cudaFuncSetAttribute((const void*)gemm_lif_qkv,
                         cudaFuncAttributeMaxDynamicSharedMemorySize, SMEM);
    cudaFuncSetAttribute((const void*)gemm_lif_p,
                         cudaFuncAttributeMaxDynamicSharedMemorySize, SMEM);

    // one-shot pre-splits (identical arithmetic to the proven inline splits)
    split_w<<<4096, 256>>>(Wq, Wk, Wv, Wp);
    split_x<<<TBCN / 4 / 256, 256>>>(x);

    // merged q/k/v: 768 identical CTAs in one scheduling pool
    gemm_lif_qkv<<<dim3(N_ / 128, C_ / 128, 24), 256, SMEM>>>(
        hq, hk, hv, qg, qb, kg, kb, vg, vb, inv);

    kv_mma<<<256, 256>>>();
    av_lif_mma<<<dim3(8, 64), 256>>>();

    // projection fused with LIF: 256 CTAs = exactly one wave
    gemm_lif_p<<<dim3(N_ / 128, C_ / 128, B_), 256, SMEM>>>(out, pg, pb, bp, inv);
}

// round 13
// speedup vs baseline: 1.0077x; 1.0077x over previous
#include <cuda_runtime.h>
#include <cuda_fp16.h>
#include <cmath>
#include <cstdint>

#define T_ 4
#define B_ 8
#define C_ 512
#define N_ 1024
#define TB 32
#define CN (C_*N_)          // 524288
#define TBCN (TB*CN)        // 16777216
#define PER_T (B_*CN)       // 4194304

// Scratch (static device globals — no runtime allocation)
__device__ __half gh_q[TBCN];        // q spikes fp16 (binary, exact)
__device__ __half gh_k[TBCN];
__device__ __half gh_v[TBCN];
__device__ __half gh_a[TBCN];        // attn spikes
__device__ __half g_kvh[TB*8*64*64]; // kv^T [tbh][e][d], counts <=1024, fp16-exact
__device__ __half g_whi[4*C_*C_];    // W hi (x 2^11) for q,k,v,p
__device__ __half g_wlo[4*C_*C_];    // W lo
__device__ __half g_xhi[TBCN];       // x hi fp16 [z][c][n]
__device__ __half g_xlo[TBCN];       // x lo

#define WSCALE     2048.0f
#define WSCALE_INV 4.8828125e-4f     // 2^-11, exact

// ============================================================================
// helpers
// ============================================================================
__device__ __forceinline__ uint32_t smem_u32(const void* p) {
    uint32_t a;
    asm("{ .reg .u64 t; cvta.to.shared.u64 t, %1; cvt.u32.u64 %0, t; }" : "=r"(a) : "l"(p));
    return a;
}
__device__ __forceinline__ uint32_t packh(__half a, __half b) {
    __half2 h = __halves2half2(a, b);
    return *(uint32_t*)&h;
}
__device__ __forceinline__ void ldmx4(uint32_t* r, uint32_t addr) {
    asm volatile("ldmatrix.sync.aligned.m8n8.x4.shared.b16 {%0,%1,%2,%3}, [%4];"
                 : "=r"(r[0]), "=r"(r[1]), "=r"(r[2]), "=r"(r[3]) : "r"(addr));
}
__device__ __forceinline__ void ldmx4t(uint32_t* r, uint32_t addr) {
    asm volatile("ldmatrix.sync.aligned.m8n8.x4.trans.shared.b16 {%0,%1,%2,%3}, [%4];"
                 : "=r"(r[0]), "=r"(r[1]), "=r"(r[2]), "=r"(r[3]) : "r"(addr));
}
__device__ __forceinline__ void mma16(float* c, const uint32_t* a, const uint32_t* b) {
    asm volatile("mma.sync.aligned.m16n8k16.row.col.f32.f16.f16.f32 "
                 "{%0,%1,%2,%3}, {%4,%5,%6,%7}, {%8,%9}, {%0,%1,%2,%3};"
                 : "+f"(c[0]), "+f"(c[1]), "+f"(c[2]), "+f"(c[3])
                 : "r"(a[0]), "r"(a[1]), "r"(a[2]), "r"(a[3]), "r"(b[0]), "r"(b[1]));
}
__device__ __forceinline__ void cp16(uint32_t dst, const void* src) {
    asm volatile("cp.async.cg.shared.global [%0], [%1], 16;" :: "r"(dst), "l"(src) : "memory");
}
#define CP_COMMIT() asm volatile("cp.async.commit_group;" ::: "memory")
#define CP_WAIT0()  asm volatile("cp.async.wait_group 0;" ::: "memory")

// exact reference LIF step: v' = v + (x - v)*0.5 ; spike >= thr ; hard reset
__device__ __forceinline__ float lif_step(float& vv, float x, float thr) {
    vv = __fadd_rn(vv, __fmul_rn(__fsub_rn(x, vv), 0.5f));
    float s = (vv >= thr) ? 1.0f : 0.0f;
    if (vv >= thr) vv = 0.0f;
    return s;
}

// ============================================================================
// Pre-split kernels (arithmetic identical to the proven inline splits)
// ============================================================================
__global__ void split_w(const float* __restrict__ w0, const float* __restrict__ w1,
                        const float* __restrict__ w2, const float* __restrict__ w3)
{
    int i = blockIdx.x * 256 + threadIdx.x;      // 0 .. 4*262144-1
    int which = i >> 18, off = i & 262143;
    const float* w = (which == 0) ? w0 : (which == 1) ? w1 : (which == 2) ? w2 : w3;
    float s = w[off] * WSCALE;
    __half hi = __float2half_rn(s);
    __half lo = __float2half_rn(s - __half2float(hi));
    g_whi[i] = hi;
    g_wlo[i] = lo;
}

__global__ void split_x(const float* __restrict__ x)
{
    size_t i4 = (size_t)blockIdx.x * 256 + threadIdx.x;   // 0 .. TBCN/4-1
    float4 v = *(const float4*)(x + i4 * 4);
    __half h0 = __float2half_rn(v.x), h1 = __float2half_rn(v.y);
    __half h2 = __float2half_rn(v.z), h3 = __float2half_rn(v.w);
    __half l0 = __float2half_rn(v.x - __half2float(h0));
    __half l1 = __float2half_rn(v.y - __half2float(h1));
    __half l2 = __float2half_rn(v.z - __half2float(h2));
    __half l3 = __float2half_rn(v.w - __half2float(h3));
    *(uint2*)(g_xhi + i4 * 4) = make_uint2(packh(h0, h1), packh(h2, h3));
    *(uint2*)(g_xlo + i4 * 4) = make_uint2(packh(l0, l1), packh(l2, l3));
}

// ============================================================================
// Core GEMM + BN (+ optional multi-step LIF) body with 2-stage cp.async
// staging (R11-proven). All operands fp16 in gmem. M128 x N128, 8 warps of
// 64x32, K-chunk 16, 1 sync/chunk.
// Stage st: Ah @st*4096, Al @8192+st*4096, Bh @16384+st*4096, Bl @24576+st*4096
// Vst (LIF membrane, 128 x 130 fp32) @32768 when DO_LIF.
// NSPLIT=3: (Whi+Wlo) x Bhi + Whi x Blo.  NSPLIT=2: (Whi+Wlo) x Bhi (binary B).
// ============================================================================
template<int NSPLIT, typename TOUT, bool DO_LIF, int NT>
__device__ __forceinline__ void gemm_body(
    const __half* __restrict__ Whi, const __half* __restrict__ Wlo,
    const __half* __restrict__ Bhi, const __half* __restrict__ Blo,
    TOUT* __restrict__ OUT,
    const float* __restrict__ gamma, const float* __restrict__ beta,
    const float* __restrict__ bias, float inv, float thr,
    char* smbuf, int b, int m0, int n0)
{
    const uint32_t sbase = smem_u32(smbuf);
    float* Vst = (float*)(smbuf + 32768);

    const int tid  = threadIdx.x;
    const int lane = tid & 31;
    const int wid  = tid >> 5;
    const int wm   = (wid >> 2) * 64;
    const int wn   = (wid & 3) * 32;

    if (DO_LIF) {
#pragma unroll
        for (int i = tid; i < 128 * 130 / 2; i += 256)
            *(float2*)&Vst[i * 2] = make_float2(0.0f, 0.0f);
    }

    const int mA  = tid >> 1;
    const int kh8 = tid & 1;
    const __half* WhiRow = Whi + (size_t)(m0 + mA) * C_ + kh8 * 8;
    const __half* WloRow = Wlo + (size_t)(m0 + mA) * C_ + kh8 * 8;
    const uint32_t abyte = (uint32_t)((mA * 2 + (kh8 ^ ((mA >> 2) & 1))) * 16);
    const int kB  = tid >> 4;
    const int seg = tid & 15;
    const uint32_t bbyte = (uint32_t)(kB * 256 + ((seg ^ (kB & 7))) * 16);

    const int mrel = (lane & 7) | (((lane >> 3) & 1) << 3);
    const int hA   = (lane >> 4) & 1;
    uint32_t offA[4];
#pragma unroll
    for (int mt = 0; mt < 4; mt++) {
        int m = wm + mt * 16 + mrel;
        offA[mt] = (uint32_t)((m * 2 + (hA ^ ((m >> 2) & 1))) * 16);
    }
    const int krel = (lane & 7) | (((lane >> 3) & 1) << 3);
    const int nrel = ((lane >> 4) & 1) * 8;
    uint32_t offB[2];
#pragma unroll
    for (int p = 0; p < 2; p++) {
        int n = wn + p * 16 + nrel;
        offB[p] = (uint32_t)(krel * 256 + (((n >> 3) ^ (krel & 7))) * 16);
    }

    if (DO_LIF) __syncthreads();

#pragma unroll 1
    for (int t = 0; t < NT; t++) {
        const size_t zoff = (size_t)(NT == 4 ? (t * 8 + b) : b) * CN;
        const __half* BhiBase = Bhi + zoff + (size_t)kB * N_ + n0 + seg * 8;
        const __half* BloBase = (NSPLIT >= 3) ? (Blo + zoff + (size_t)kB * N_ + n0 + seg * 8)
                                              : (const __half*)nullptr;

        float acc[4][4][4];
#pragma unroll
        for (int i = 0; i < 4; i++)
#pragma unroll
            for (int j = 0; j < 4; j++)
#pragma unroll
                for (int e = 0; e < 4; e++) acc[i][j][e] = 0.0f;

        auto ISSUE = [&](int ch) {
            const int st = ch & 1;
            const int kb = ch * 16;
            cp16(sbase + st * 4096 + abyte,         WhiRow + kb);
            cp16(sbase + 8192 + st * 4096 + abyte,  WloRow + kb);
            cp16(sbase + 16384 + st * 4096 + bbyte, BhiBase + (size_t)kb * N_);
            if (NSPLIT >= 3)
                cp16(sbase + 24576 + st * 4096 + bbyte, BloBase + (size_t)kb * N_);
            CP_COMMIT();
        };

        auto COMP = [&](int st) {
            const uint32_t aHi = sbase + st * 4096;
            const uint32_t aLo = sbase + 8192 + st * 4096;
            const uint32_t bHi = sbase + 16384 + st * 4096;
            const uint32_t bLo = sbase + 24576 + st * 4096;

            uint32_t ah[4][4], bh[4][2];
#pragma unroll
            for (int mt = 0; mt < 4; mt++) ldmx4(ah[mt], aHi + offA[mt]);
#pragma unroll
            for (int p = 0; p < 2; p++) {
                uint32_t tr[4];
                ldmx4t(tr, bHi + offB[p]);
                bh[2 * p][0] = tr[0]; bh[2 * p][1] = tr[1];
                bh[2 * p + 1][0] = tr[2]; bh[2 * p + 1][1] = tr[3];
            }
#pragma unroll
            for (int mt = 0; mt < 4; mt++)
#pragma unroll
                for (int nt = 0; nt < 4; nt++) mma16(acc[mt][nt], ah[mt], bh[nt]);
            if (NSPLIT >= 3) {
                uint32_t bl[4][2];
#pragma unroll
                for (int p = 0; p < 2; p++) {
                    uint32_t tr[4];
                    ldmx4t(tr, bLo + offB[p]);
                    bl[2 * p][0] = tr[0]; bl[2 * p][1] = tr[1];
                    bl[2 * p + 1][0] = tr[2]; bl[2 * p + 1][1] = tr[3];
                }
#pragma unroll
                for (int mt = 0; mt < 4; mt++)
#pragma unroll
                    for (int nt = 0; nt < 4; nt++) mma16(acc[mt][nt], ah[mt], bl[nt]);
            }
#pragma unroll
            for (int mt = 0; mt < 4; mt++) ldmx4(ah[mt], aLo + offA[mt]);
#pragma unroll
            for (int mt = 0; mt < 4; mt++)
#pragma unroll
                for (int nt = 0; nt < 4; nt++) mma16(acc[mt][nt], ah[mt], bh[nt]);
        };

        ISSUE(0);
#pragma unroll 1
        for (int ch = 0; ch < 32; ch++) {
            CP_WAIT0();
            __syncthreads();
            if (ch < 31) ISSUE(ch + 1);
            COMP(ch & 1);
        }

        // Epilogue: descale (exact 2^-11), BN (exact jax op order), optional LIF.
        {
            const int rb = m0 + wm + (lane >> 2);
            const int cb = n0 + wn + 2 * (lane & 3);
            const int rlb = wm + (lane >> 2);
            const int clb = wn + 2 * (lane & 3);
            TOUT* Oz = OUT + zoff;
#pragma unroll
            for (int mt = 0; mt < 4; mt++) {
                int r0 = rb + mt * 16, r1 = r0 + 8;
                float g0 = gamma[r0], g1 = gamma[r1];
                float e0 = beta[r0],  e1 = beta[r1];
                float b0 = bias ? bias[r0] : 0.0f;
                float b1 = bias ? bias[r1] : 0.0f;
                float* vrow0 = &Vst[(rlb + mt * 16) * 130 + clb];
                float* vrow1 = vrow0 + 8 * 130;
#pragma unroll
                for (int nt = 0; nt < 4; nt++) {
                    int cc = cb + nt * 8;
                    float* c = acc[mt][nt];
                    float y0 = __fmul_rn(c[0], WSCALE_INV);
                    float y1 = __fmul_rn(c[1], WSCALE_INV);
                    float y2 = __fmul_rn(c[2], WSCALE_INV);
                    float y3 = __fmul_rn(c[3], WSCALE_INV);
                    if (bias) { y0 = __fadd_rn(y0, b0); y1 = __fadd_rn(y1, b0);
                                y2 = __fadd_rn(y2, b1); y3 = __fadd_rn(y3, b1); }
                    y0 = __fadd_rn(__fmul_rn(__fmul_rn(g0, y0), inv), e0);
                    y1 = __fadd_rn(__fmul_rn(__fmul_rn(g0, y1), inv), e0);
                    y2 = __fadd_rn(__fmul_rn(__fmul_rn(g1, y2), inv), e1);
                    y3 = __fadd_rn(__fmul_rn(__fmul_rn(g1, y3), inv), e1);
                    if (DO_LIF) {
                        float vv0 = vrow0[nt * 8],     vv1 = vrow0[nt * 8 + 1];
                        float vv2 = vrow1[nt * 8],     vv3 = vrow1[nt * 8 + 1];
                        float s0 = lif_step(vv0, y0, thr);
                        float s1 = lif_step(vv1, y1, thr);
                        float s2 = lif_step(vv2, y2, thr);
                        float s3 = lif_step(vv3, y3, thr);
                        vrow0[nt * 8] = vv0; vrow0[nt * 8 + 1] = vv1;
                        vrow1[nt * 8] = vv2; vrow1[nt * 8 + 1] = vv3;
                        if (sizeof(TOUT) == 2) {
                            *(uint32_t*)((__half*)Oz + (size_t)r0 * N_ + cc) =
                                packh(__float2half_rn(s0), __float2half_rn(s1));
                            *(uint32_t*)((__half*)Oz + (size_t)r1 * N_ + cc) =
                                packh(__float2half_rn(s2), __float2half_rn(s3));
                        } else {
                            *(float2*)((float*)Oz + (size_t)r0 * N_ + cc) = make_float2(s0, s1);
                            *(float2*)((float*)Oz + (size_t)r1 * N_ + cc) = make_float2(s2, s3);
                        }
                    } else {
                        *(float2*)((float*)Oz + (size_t)r0 * N_ + cc) = make_float2(y0, y1);
                        *(float2*)((float*)Oz + (size_t)r1 * N_ + cc) = make_float2(y2, y3);
                    }
                }
            }
        }
    }
}

// ============================================================================
// Merged q/k/v GEMM+BN+LIF: grid z = mi*8 + b (768 CTAs, one pool) — R11-exact
// ============================================================================
__global__ __launch_bounds__(256, 2) void gemm_lif_qkv(
    __half* __restrict__ oq, __half* __restrict__ ok, __half* __restrict__ ov,
    const float* __restrict__ qg, const float* __restrict__ qb,
    const float* __restrict__ kg, const float* __restrict__ kb,
    const float* __restrict__ vg, const float* __restrict__ vb,
    float inv)
{
    extern __shared__ char smbuf[];
    const int z  = blockIdx.z;
    const int mi = z >> 3;
    const int b  = z & 7;
    const __half* Whi = g_whi + (size_t)mi * C_ * C_;
    const __half* Wlo = g_wlo + (size_t)mi * C_ * C_;
    __half* OUT    = (mi == 0) ? oq : (mi == 1) ? ok : ov;
    const float* g = (mi == 0) ? qg : (mi == 1) ? kg : vg;
    const float* e = (mi == 0) ? qb : (mi == 1) ? kb : vb;
    gemm_body<3, __half, true, 4>(Whi, Wlo, g_xhi, g_xlo, OUT, g, e, nullptr,
                                  inv, 1.0f, smbuf, b,
                                  blockIdx.y * 128, blockIdx.x * 128);
}

// ============================================================================
// Projection GEMM fused with BN + LIF: z = 0..7 (256 CTAs, under one wave).
// Binary fp16 B (exact), 2-stage pipeline, SMEM 99328 (proven 2 CTA/SM).
// Spikes written straight to d_out.
// ============================================================================
__global__ __launch_bounds__(256, 2) void gemm_lif_p(
    float* __restrict__ OUT,
    const float* __restrict__ gamma, const float* __restrict__ beta,
    const float* __restrict__ bias, float inv)
{
    extern __shared__ char smbuf[];
    const __half* Whi = g_whi + (size_t)3 * C_ * C_;
    const __half* Wlo = g_wlo + (size_t)3 * C_ * C_;
    gemm_body<2, float, true, 4>(Whi, Wlo, gh_a, nullptr, OUT,
                                 gamma, beta, bias, inv, 1.0f,
                                 smbuf, blockIdx.z,
                                 blockIdx.y * 128, blockIdx.x * 128);
}

// ============================================================================
// kv via tensor cores (R7-proven): kv[d][e] -> g_kvh[tbh][e][d]
// ============================================================================
__global__ __launch_bounds__(256) void kv_mma()
{
    __shared__ char sK[16384];
    __shared__ char sV[16384];

    const int tbh = blockIdx.x;
    const int tb = tbh >> 3, h = tbh & 7;
    const __half* K = gh_k + (size_t)tb * CN + (size_t)h * 64 * N_;
    const __half* V = gh_v + (size_t)tb * CN + (size_t)h * 64 * N_;

    const int tid = threadIdx.x;
    const int lane = tid & 31;
    const int w = tid >> 5;
    const int mt = (w & 3) * 16;
    const int nh = (w >> 2) * 32;

    const uint32_t skb = smem_u32(sK);
    const uint32_t svb = smem_u32(sV);

    float acc[4][4];
#pragma unroll
    for (int i = 0; i < 4; i++)
#pragma unroll
        for (int j = 0; j < 4; j++) acc[i][j] = 0.0f;

    const __half* src = (tid < 128) ? K : V;
    char* dstp = (tid < 128) ? sK : sV;
    const int lt = tid & 127;

#pragma unroll 1
    for (int c = 0; c < 8; c++) {
        __syncthreads();
#pragma unroll
        for (int i = 0; i < 8; i++) {
            int idx = lt + i * 128;
            int row = idx >> 4, seg = idx & 15;
            int phys = seg ^ (row & 7);
            *(uint4*)(dstp + row * 256 + phys * 16) =
                *(const uint4*)(src + (size_t)row * N_ + c * 128 + seg * 8);
        }
        __syncthreads();

#pragma unroll
        for (int j = 0; j < 8; j++) {
            uint32_t a[4];
            {
                int row = mt + (lane & 7) + ((lane >> 3) & 1) * 8;
                int seg = 2 * j + (lane >> 4);
                ldmx4(a, skb + row * 256 + (seg ^ (row & 7)) * 16);
            }
#pragma unroll
            for (int p = 0; p < 2; p++) {
                uint32_t r[4];
                int row = nh + p * 16 + (lane & 7) + ((lane >> 4) & 1) * 8;
                int seg = 2 * j + ((lane >> 3) & 1);
                ldmx4(r, svb + row * 256 + (seg ^ (row & 7)) * 16);
                mma16(acc[2 * p],     a, &r[0]);
                mma16(acc[2 * p + 1], a, &r[2]);
            }
        }
    }

    __half* out = g_kvh + (size_t)tbh * 4096;
    const int d0 = mt + (lane >> 2);
    const int eb = nh + 2 * (lane & 3);
#pragma unroll
    for (int nt = 0; nt < 4; nt++) {
        int e = eb + nt * 8;
        out[(size_t)e * 64 + d0]           = __float2half_rn(acc[nt][0]);
        out[(size_t)(e + 1) * 64 + d0]     = __float2half_rn(acc[nt][1]);
        out[(size_t)e * 64 + d0 + 8]       = __float2half_rn(acc[nt][2]);
        out[(size_t)(e + 1) * 64 + d0 + 8] = __float2half_rn(acc[nt][3]);
    }
}

// ============================================================================
// av via tensor cores + fused attn-LIF (R7-proven)
// ============================================================================
__global__ __launch_bounds__(256, 2) void av_lif_mma()
{
    __shared__ char sA[8192];
    __shared__ char sQ[32768];

    const int bh = blockIdx.y;
    const int b = bh >> 3, h = bh & 7;
    const int n0 = blockIdx.x * 128;

    const int tid = threadIdx.x;
    const int lane = tid & 31;
    const int w = tid >> 5;

    const uint32_t sab = smem_u32(sA);
    const uint32_t sqb = smem_u32(sQ);

    const int mrel = (lane & 7) + ((lane >> 3) & 1) * 8;
    const int hA = (lane >> 4) & 1;
    const int krel = (lane & 7) | (((lane >> 3) & 1) << 3);
    const int nrel = ((lane >> 4) & 1) * 8;
    const int nseg = (w * 16 + nrel) >> 3;

    float vst[4][2][4];
#pragma unroll
    for (int i = 0; i < 4; i++)
#pragma unroll
        for (int j = 0; j < 2; j++)
#pragma unroll
            for (int e = 0; e < 4; e++) vst[i][j][e] = 0.0f;

#pragma unroll 1
    for (int t = 0; t < 4; t++) {
        const int tb = t * 8 + b;
        const __half* KV = g_kvh + ((size_t)tb * 8 + h) * 4096;
        const __half* Q  = gh_q + (size_t)tb * CN + (size_t)h * 64 * N_;

        __syncthreads();
#pragma unroll
        for (int i = 0; i < 2; i++) {
            int idx = tid + i * 256;
            int e = idx >> 3, seg = idx & 7;
            int phys = seg ^ (e & 7);
            *(uint4*)(sA + e * 128 + phys * 16) =
                *(const uint4*)(KV + (size_t)e * 64 + seg * 8);
        }
#pragma unroll
        for (int i = 0; i < 4; i++) {
            int idx = tid + i * 256;
            int d = idx >> 4, seg = idx & 15;
            int phys = seg ^ (d & 7);
            *(uint4*)(sQ + d * 256 + phys * 16) =
                *(const uint4*)(Q + (size_t)d * N_ + n0 + seg * 8);
        }
        __syncthreads();

        float acc[4][2][4];
#pragma unroll
        for (int i = 0; i < 4; i++)
#pragma unroll
            for (int j = 0; j < 2; j++)
#pragma unroll
                for (int e = 0; e < 4; e++) acc[i][j][e] = 0.0f;

#pragma unroll
        for (int j = 0; j < 4; j++) {
            uint32_t bq[2][2];
            {
                uint32_t tr[4];
                int kr = j * 16 + krel;
                ldmx4t(tr, sqb + kr * 256 + ((nseg ^ (kr & 7))) * 16);
                bq[0][0] = tr[0]; bq[0][1] = tr[1];
                bq[1][0] = tr[2]; bq[1][1] = tr[3];
            }
#pragma unroll
            for (int mt = 0; mt < 4; mt++) {
                uint32_t a[4];
                int row = mt * 16 + mrel;
                int seg = 2 * j + hA;
                ldmx4(a, sab + row * 128 + ((seg ^ (row & 7))) * 16);
                mma16(acc[mt][0], a, bq[0]);
                mma16(acc[mt][1], a, bq[1]);
            }
        }

        __half* A = gh_a + (size_t)tb * CN + (size_t)h * 64 * N_;
        const int cb = n0 + w * 16 + 2 * (lane & 3);
#pragma unroll
        for (int mt = 0; mt < 4; mt++) {
            int e0 = mt * 16 + (lane >> 2), e1 = e0 + 8;
#pragma unroll
            for (int nt = 0; nt < 2; nt++) {
                int cc = cb + nt * 8;
                float* c = acc[mt][nt];
                float* vv = vst[mt][nt];
                float s0 = lif_step(vv[0], __fmul_rn(c[0], 0.125f), 0.5f);
                float s1 = lif_step(vv[1], __fmul_rn(c[1], 0.125f), 0.5f);
                float s2 = lif_step(vv[2], __fmul_rn(c[2], 0.125f), 0.5f);
                float s3 = lif_step(vv[3], __fmul_rn(c[3], 0.125f), 0.5f);
                *(uint32_t*)(A + (size_t)e0 * N_ + cc) =
                    packh(__float2half_rn(s0), __float2half_rn(s1));
                *(uint32_t*)(A + (size_t)e1 * N_ + cc) =
                    packh(__float2half_rn(s2), __float2half_rn(s3));
            }
        }
    }
}

// ============================================================================
extern "C" void kernel_launch(void* const* d_in, const int* in_sizes, int n_in,
                              void* d_out, int out_size)
{
    const float* x   = (const float*)d_in[0];
    const float* Wq  = (const float*)d_in[1];
    const float* qg  = (const float*)d_in[2];
    const float* qb  = (const float*)d_in[3];
    const float* Wk  = (const float*)d_in[4];
    const float* kg  = (const float*)d_in[5];
    const float* kb  = (const float*)d_in[6];
    const float* Wv  = (const float*)d_in[7];
    const float* vg  = (const float*)d_in[8];
    const float* vb  = (const float*)d_in[9];
    const float* Wp  = (const float*)d_in[10];
    const float* bp  = (const float*)d_in[11];
    const float* pg  = (const float*)d_in[12];
    const float* pb  = (const float*)d_in[13];
    float* out = (float*)d_out;

    __half *hq, *hk, *hv;
    cudaGetSymbolAddress((void**)&hq, gh_q);
    cudaGetSymbolAddress((void**)&hk, gh_k);
    cudaGetSymbolAddress((void**)&hv, gh_v);

    float one_eps = 1.0f + 1e-5f;
    float inv = (float)(1.0 / sqrt((double)one_eps));

    const int SMEM = 32768 + 128 * 130 * 4;   // 99328 (panels + LIF state), 2 CTA/SM
    cudaFuncSetAttribute((const void*)gemm_lif_qkv,
                         cudaFuncAttributeMaxDynamicSharedMemorySize, SMEM);
    cudaFuncSetAttribute((const void*)gemm_lif_p,
                         cudaFuncAttributeMaxDynamicSharedMemorySize, SMEM);

    // one-shot pre-splits (identical arithmetic to the proven inline splits)
    split_w<<<4096, 256>>>(Wq, Wk, Wv, Wp);
    split_x<<<TBCN / 4 / 256, 256>>>(x);

    // merged q/k/v: 768 identical CTAs in one scheduling pool
    gemm_lif_qkv<<<dim3(N_ / 128, C_ / 128, 24), 256, SMEM>>>(
        hq, hk, hv, qg, qb, kg, kb, vg, vb, inv);

    kv_mma<<<256, 256>>>();
    av_lif_mma<<<dim3(8, 64), 256>>>();

    // projection fused with BN+LIF: 256 CTAs, spikes straight to d_out
    gemm_lif_p<<<dim3(N_ / 128, C_ / 128, B_), 256, SMEM>>>(out, pg, pb, bp, inv);
}

// round 14
// speedup vs baseline: 1.0608x; 1.0527x over previous
#include <cuda_runtime.h>
#include <cuda_fp16.h>
#include <cmath>
#include <cstdint>

#define T_ 4
#define B_ 8
#define C_ 512
#define N_ 1024
#define TB 32
#define CN (C_*N_)          // 524288
#define TBCN (TB*CN)        // 16777216
#define PER_T (B_*CN)       // 4194304

// Scratch (static device globals — no runtime allocation)
__device__ __half gh_q[TBCN];        // q spikes fp16 (binary, exact)
__device__ __half gh_k[TBCN];
__device__ __half gh_v[TBCN];
__device__ __half gh_a[TBCN];        // attn spikes
__device__ __half g_kvh[TB*8*64*64]; // kv^T [tbh][e][d], counts <=1024, fp16-exact
__device__ float  g_p[TBCN];         // projection pre-LIF (BN output, fp32)
__device__ __half g_whi[4*C_*C_];    // W hi (x 2^11) for q,k,v,p
__device__ __half g_wlo[4*C_*C_];    // W lo
__device__ __half g_xhi[TBCN];       // x hi fp16 [z][c][n]
__device__ __half g_xlo[TBCN];       // x lo

#define WSCALE     2048.0f
#define WSCALE_INV 4.8828125e-4f     // 2^-11, exact

// ============================================================================
// helpers
// ============================================================================
__device__ __forceinline__ uint32_t smem_u32(const void* p) {
    uint32_t a;
    asm("{ .reg .u64 t; cvta.to.shared.u64 t, %1; cvt.u32.u64 %0, t; }" : "=r"(a) : "l"(p));
    return a;
}
__device__ __forceinline__ uint32_t packh(__half a, __half b) {
    __half2 h = __halves2half2(a, b);
    return *(uint32_t*)&h;
}
__device__ __forceinline__ void ldmx4(uint32_t* r, uint32_t addr) {
    asm volatile("ldmatrix.sync.aligned.m8n8.x4.shared.b16 {%0,%1,%2,%3}, [%4];"
                 : "=r"(r[0]), "=r"(r[1]), "=r"(r[2]), "=r"(r[3]) : "r"(addr));
}
__device__ __forceinline__ void ldmx4t(uint32_t* r, uint32_t addr) {
    asm volatile("ldmatrix.sync.aligned.m8n8.x4.trans.shared.b16 {%0,%1,%2,%3}, [%4];"
                 : "=r"(r[0]), "=r"(r[1]), "=r"(r[2]), "=r"(r[3]) : "r"(addr));
}
__device__ __forceinline__ void mma16(float* c, const uint32_t* a, const uint32_t* b) {
    asm volatile("mma.sync.aligned.m16n8k16.row.col.f32.f16.f16.f32 "
                 "{%0,%1,%2,%3}, {%4,%5,%6,%7}, {%8,%9}, {%0,%1,%2,%3};"
                 : "+f"(c[0]), "+f"(c[1]), "+f"(c[2]), "+f"(c[3])
                 : "r"(a[0]), "r"(a[1]), "r"(a[2]), "r"(a[3]), "r"(b[0]), "r"(b[1]));
}
__device__ __forceinline__ void cp16(uint32_t dst, const void* src) {
    asm volatile("cp.async.cg.shared.global [%0], [%1], 16;" :: "r"(dst), "l"(src) : "memory");
}
#define CP_COMMIT() asm volatile("cp.async.commit_group;" ::: "memory")
#define CP_WAIT0()  asm volatile("cp.async.wait_group 0;" ::: "memory")

// exact reference LIF step: v' = v + (x - v)*0.5 ; spike >= thr ; hard reset
__device__ __forceinline__ float lif_step(float& vv, float x, float thr) {
    vv = __fadd_rn(vv, __fmul_rn(__fsub_rn(x, vv), 0.5f));
    float s = (vv >= thr) ? 1.0f : 0.0f;
    if (vv >= thr) vv = 0.0f;
    return s;
}

// ============================================================================
// Pre-split kernels (arithmetic identical to the proven inline splits)
// ============================================================================
__global__ void split_w(const float* __restrict__ w0, const float* __restrict__ w1,
                        const float* __restrict__ w2, const float* __restrict__ w3)
{
    int i = blockIdx.x * 256 + threadIdx.x;      // 0 .. 4*262144-1
    int which = i >> 18, off = i & 262143;
    const float* w = (which == 0) ? w0 : (which == 1) ? w1 : (which == 2) ? w2 : w3;
    float s = w[off] * WSCALE;
    __half hi = __float2half_rn(s);
    __half lo = __float2half_rn(s - __half2float(hi));
    g_whi[i] = hi;
    g_wlo[i] = lo;
}

__global__ void split_x(const float* __restrict__ x)
{
    size_t i4 = (size_t)blockIdx.x * 256 + threadIdx.x;   // 0 .. TBCN/4-1
    float4 v = *(const float4*)(x + i4 * 4);
    __half h0 = __float2half_rn(v.x), h1 = __float2half_rn(v.y);
    __half h2 = __float2half_rn(v.z), h3 = __float2half_rn(v.w);
    __half l0 = __float2half_rn(v.x - __half2float(h0));
    __half l1 = __float2half_rn(v.y - __half2float(h1));
    __half l2 = __float2half_rn(v.z - __half2float(h2));
    __half l3 = __float2half_rn(v.w - __half2float(h3));
    *(uint2*)(g_xhi + i4 * 4) = make_uint2(packh(h0, h1), packh(h2, h3));
    *(uint2*)(g_xlo + i4 * 4) = make_uint2(packh(l0, l1), packh(l2, l3));
}

// ============================================================================
// qkv GEMM + BN + multi-step LIF, 2-stage cp.async (R11-exact, proven).
// M128 x N128, 8 warps of 64x32, K-chunk 16, 1 sync/chunk.
// ============================================================================
__global__ __launch_bounds__(256, 2) void gemm_lif_qkv(
    __half* __restrict__ oq, __half* __restrict__ ok, __half* __restrict__ ov,
    const float* __restrict__ qg, const float* __restrict__ qb,
    const float* __restrict__ kg, const float* __restrict__ kb_,
    const float* __restrict__ vg, const float* __restrict__ vb,
    float inv)
{
    extern __shared__ char smbuf[];
    const uint32_t sbase = smem_u32(smbuf);
    float* Vst = (float*)(smbuf + 32768);

    const int z  = blockIdx.z;
    const int mi = z >> 3;
    const int b  = z & 7;
    const __half* Whi = g_whi + (size_t)mi * C_ * C_;
    const __half* Wlo = g_wlo + (size_t)mi * C_ * C_;
    __half* OUT    = (mi == 0) ? oq : (mi == 1) ? ok : ov;
    const float* gamma = (mi == 0) ? qg : (mi == 1) ? kg : vg;
    const float* beta  = (mi == 0) ? qb : (mi == 1) ? kb_ : vb;
    const int m0 = blockIdx.y * 128;
    const int n0 = blockIdx.x * 128;

    const int tid  = threadIdx.x;
    const int lane = tid & 31;
    const int wid  = tid >> 5;
    const int wm   = (wid >> 2) * 64;
    const int wn   = (wid & 3) * 32;

#pragma unroll
    for (int i = tid; i < 128 * 130 / 2; i += 256)
        *(float2*)&Vst[i * 2] = make_float2(0.0f, 0.0f);

    const int mA  = tid >> 1;
    const int kh8 = tid & 1;
    const __half* WhiRow = Whi + (size_t)(m0 + mA) * C_ + kh8 * 8;
    const __half* WloRow = Wlo + (size_t)(m0 + mA) * C_ + kh8 * 8;
    const uint32_t abyte = (uint32_t)((mA * 2 + (kh8 ^ ((mA >> 2) & 1))) * 16);
    const int kB  = tid >> 4;
    const int seg = tid & 15;
    const uint32_t bbyte = (uint32_t)(kB * 256 + ((seg ^ (kB & 7))) * 16);

    const int mrel = (lane & 7) | (((lane >> 3) & 1) << 3);
    const int hA   = (lane >> 4) & 1;
    uint32_t offA[4];
#pragma unroll
    for (int mt = 0; mt < 4; mt++) {
        int m = wm + mt * 16 + mrel;
        offA[mt] = (uint32_t)((m * 2 + (hA ^ ((m >> 2) & 1))) * 16);
    }
    const int krel = (lane & 7) | (((lane >> 3) & 1) << 3);
    const int nrel = ((lane >> 4) & 1) * 8;
    uint32_t offB[2];
#pragma unroll
    for (int p = 0; p < 2; p++) {
        int n = wn + p * 16 + nrel;
        offB[p] = (uint32_t)(krel * 256 + (((n >> 3) ^ (krel & 7))) * 16);
    }

    __syncthreads();

#pragma unroll 1
    for (int t = 0; t < 4; t++) {
        const size_t zoff = (size_t)(t * 8 + b) * CN;
        const __half* BhiBase = g_xhi + zoff + (size_t)kB * N_ + n0 + seg * 8;
        const __half* BloBase = g_xlo + zoff + (size_t)kB * N_ + n0 + seg * 8;

        float acc[4][4][4];
#pragma unroll
        for (int i = 0; i < 4; i++)
#pragma unroll
            for (int j = 0; j < 4; j++)
#pragma unroll
                for (int e = 0; e < 4; e++) acc[i][j][e] = 0.0f;

        auto ISSUE = [&](int ch) {
            const int st = ch & 1;
            const int kb = ch * 16;
            cp16(sbase + st * 4096 + abyte,         WhiRow + kb);
            cp16(sbase + 8192 + st * 4096 + abyte,  WloRow + kb);
            cp16(sbase + 16384 + st * 4096 + bbyte, BhiBase + (size_t)kb * N_);
            cp16(sbase + 24576 + st * 4096 + bbyte, BloBase + (size_t)kb * N_);
            CP_COMMIT();
        };

        auto COMP = [&](int st) {
            const uint32_t aHi = sbase + st * 4096;
            const uint32_t aLo = sbase + 8192 + st * 4096;
            const uint32_t bHi = sbase + 16384 + st * 4096;
            const uint32_t bLo = sbase + 24576 + st * 4096;

            uint32_t ah[4][4], bh[4][2];
#pragma unroll
            for (int mt = 0; mt < 4; mt++) ldmx4(ah[mt], aHi + offA[mt]);
#pragma unroll
            for (int p = 0; p < 2; p++) {
                uint32_t tr[4];
                ldmx4t(tr, bHi + offB[p]);
                bh[2 * p][0] = tr[0]; bh[2 * p][1] = tr[1];
                bh[2 * p + 1][0] = tr[2]; bh[2 * p + 1][1] = tr[3];
            }
#pragma unroll
            for (int mt = 0; mt < 4; mt++)
#pragma unroll
                for (int nt = 0; nt < 4; nt++) mma16(acc[mt][nt], ah[mt], bh[nt]);
            {
                uint32_t bl[4][2];
#pragma unroll
                for (int p = 0; p < 2; p++) {
                    uint32_t tr[4];
                    ldmx4t(tr, bLo + offB[p]);
                    bl[2 * p][0] = tr[0]; bl[2 * p][1] = tr[1];
                    bl[2 * p + 1][0] = tr[2]; bl[2 * p + 1][1] = tr[3];
                }
#pragma unroll
                for (int mt = 0; mt < 4; mt++)
#pragma unroll
                    for (int nt = 0; nt < 4; nt++) mma16(acc[mt][nt], ah[mt], bl[nt]);
            }
#pragma unroll
            for (int mt = 0; mt < 4; mt++) ldmx4(ah[mt], aLo + offA[mt]);
#pragma unroll
            for (int mt = 0; mt < 4; mt++)
#pragma unroll
                for (int nt = 0; nt < 4; nt++) mma16(acc[mt][nt], ah[mt], bh[nt]);
        };

        ISSUE(0);
#pragma unroll 1
        for (int ch = 0; ch < 32; ch++) {
            CP_WAIT0();
            __syncthreads();
            if (ch < 31) ISSUE(ch + 1);
            COMP(ch & 1);
        }

        // Epilogue: descale, BN (exact jax op order), LIF (state in SMEM)
        {
            const int rb = m0 + wm + (lane >> 2);
            const int cb = n0 + wn + 2 * (lane & 3);
            const int rlb = wm + (lane >> 2);
            const int clb = wn + 2 * (lane & 3);
            __half* Oz = OUT + zoff;
#pragma unroll
            for (int mt = 0; mt < 4; mt++) {
                int r0 = rb + mt * 16, r1 = r0 + 8;
                float g0 = gamma[r0], g1 = gamma[r1];
                float e0 = beta[r0],  e1 = beta[r1];
                float* vrow0 = &Vst[(rlb + mt * 16) * 130 + clb];
                float* vrow1 = vrow0 + 8 * 130;
#pragma unroll
                for (int nt = 0; nt < 4; nt++) {
                    int cc = cb + nt * 8;
                    float* c = acc[mt][nt];
                    float y0 = __fmul_rn(c[0], WSCALE_INV);
                    float y1 = __fmul_rn(c[1], WSCALE_INV);
                    float y2 = __fmul_rn(c[2], WSCALE_INV);
                    float y3 = __fmul_rn(c[3], WSCALE_INV);
                    y0 = __fadd_rn(__fmul_rn(__fmul_rn(g0, y0), inv), e0);
                    y1 = __fadd_rn(__fmul_rn(__fmul_rn(g0, y1), inv), e0);
                    y2 = __fadd_rn(__fmul_rn(__fmul_rn(g1, y2), inv), e1);
                    y3 = __fadd_rn(__fmul_rn(__fmul_rn(g1, y3), inv), e1);
                    float vv0 = vrow0[nt * 8],     vv1 = vrow0[nt * 8 + 1];
                    float vv2 = vrow1[nt * 8],     vv3 = vrow1[nt * 8 + 1];
                    float s0 = lif_step(vv0, y0, 1.0f);
                    float s1 = lif_step(vv1, y1, 1.0f);
                    float s2 = lif_step(vv2, y2, 1.0f);
                    float s3 = lif_step(vv3, y3, 1.0f);
                    vrow0[nt * 8] = vv0; vrow0[nt * 8 + 1] = vv1;
                    vrow1[nt * 8] = vv2; vrow1[nt * 8 + 1] = vv3;
                    *(uint32_t*)(Oz + (size_t)r0 * N_ + cc) =
                        packh(__float2half_rn(s0), __float2half_rn(s1));
                    *(uint32_t*)(Oz + (size_t)r1 * N_ + cc) =
                        packh(__float2half_rn(s2), __float2half_rn(s3));
                }
            }
        }
    }
}

// ============================================================================
// Projection GEMM + BN, K-chunk 32 (two k16 sub-panels per barrier epoch),
// unfused, binary fp16 B (exact). Grid (8 n, 4 m, 32 z). Writes fp32 to g_p.
// Same layout formulas / MMA order as R11 per k16 -> bit-identical result.
// Stage st @ st*24576: Ah sub j @ j*4096, Al @8192+j*4096, Bh @16384+j*4096.
// ============================================================================
__global__ __launch_bounds__(256, 2) void gemm_bn_p32(
    float* __restrict__ OUT,
    const float* __restrict__ gamma, const float* __restrict__ beta,
    const float* __restrict__ bias, float inv)
{
    __shared__ char smbuf[49152];
    const uint32_t sbase = smem_u32(smbuf);

    const __half* Whi = g_whi + (size_t)3 * C_ * C_;
    const __half* Wlo = g_wlo + (size_t)3 * C_ * C_;
    const int z  = blockIdx.z;
    const int m0 = blockIdx.y * 128;
    const int n0 = blockIdx.x * 128;

    const int tid  = threadIdx.x;
    const int lane = tid & 31;
    const int wid  = tid >> 5;
    const int wm   = (wid >> 2) * 64;
    const int wn   = (wid & 3) * 32;

    const int mA  = tid >> 1;
    const int kh8 = tid & 1;
    const __half* WhiRow = Whi + (size_t)(m0 + mA) * C_ + kh8 * 8;
    const __half* WloRow = Wlo + (size_t)(m0 + mA) * C_ + kh8 * 8;
    const uint32_t abyte = (uint32_t)((mA * 2 + (kh8 ^ ((mA >> 2) & 1))) * 16);
    const int kB  = tid >> 4;
    const int seg = tid & 15;
    const uint32_t bbyte = (uint32_t)(kB * 256 + ((seg ^ (kB & 7))) * 16);

    const size_t zoff = (size_t)z * CN;
    const __half* BBase = gh_a + zoff + (size_t)kB * N_ + n0 + seg * 8;

    const int mrel = (lane & 7) | (((lane >> 3) & 1) << 3);
    const int hA   = (lane >> 4) & 1;
    uint32_t offA[4];
#pragma unroll
    for (int mt = 0; mt < 4; mt++) {
        int m = wm + mt * 16 + mrel;
        offA[mt] = (uint32_t)((m * 2 + (hA ^ ((m >> 2) & 1))) * 16);
    }
    const int krel = (lane & 7) | (((lane >> 3) & 1) << 3);
    const int nrel = ((lane >> 4) & 1) * 8;
    uint32_t offB[2];
#pragma unroll
    for (int p = 0; p < 2; p++) {
        int n = wn + p * 16 + nrel;
        offB[p] = (uint32_t)(krel * 256 + (((n >> 3) ^ (krel & 7))) * 16);
    }

    float acc[4][4][4];
#pragma unroll
    for (int i = 0; i < 4; i++)
#pragma unroll
        for (int j = 0; j < 4; j++)
#pragma unroll
            for (int e = 0; e < 4; e++) acc[i][j][e] = 0.0f;

    auto ISSUE = [&](int ch) {                 // ch = k32 chunk index (0..15)
        const uint32_t st = (uint32_t)(ch & 1) * 24576u;
        const int kb = ch * 32;
#pragma unroll
        for (int j = 0; j < 2; j++) {
            cp16(sbase + st + j * 4096 + abyte,          WhiRow + kb + j * 16);
            cp16(sbase + st + 8192 + j * 4096 + abyte,   WloRow + kb + j * 16);
            cp16(sbase + st + 16384 + j * 4096 + bbyte,  BBase + (size_t)(kb + j * 16) * N_);
        }
        CP_COMMIT();
    };

    auto COMP = [&](int ch) {
        const uint32_t st = (uint32_t)(ch & 1) * 24576u;
#pragma unroll
        for (int j = 0; j < 2; j++) {          // k16 sub-panels in k order
            const uint32_t aHi = sbase + st + j * 4096;
            const uint32_t aLo = sbase + st + 8192 + j * 4096;
            const uint32_t bHi = sbase + st + 16384 + j * 4096;

            uint32_t ah[4][4], bh[4][2];
#pragma unroll
            for (int mt = 0; mt < 4; mt++) ldmx4(ah[mt], aHi + offA[mt]);
#pragma unroll
            for (int p = 0; p < 2; p++) {
                uint32_t tr[4];
                ldmx4t(tr, bHi + offB[p]);
                bh[2 * p][0] = tr[0]; bh[2 * p][1] = tr[1];
                bh[2 * p + 1][0] = tr[2]; bh[2 * p + 1][1] = tr[3];
            }
#pragma unroll
            for (int mt = 0; mt < 4; mt++)
#pragma unroll
                for (int nt = 0; nt < 4; nt++) mma16(acc[mt][nt], ah[mt], bh[nt]);
#pragma unroll
            for (int mt = 0; mt < 4; mt++) ldmx4(ah[mt], aLo + offA[mt]);
#pragma unroll
            for (int mt = 0; mt < 4; mt++)
#pragma unroll
                for (int nt = 0; nt < 4; nt++) mma16(acc[mt][nt], ah[mt], bh[nt]);
        }
    };

    ISSUE(0);
#pragma unroll 1
    for (int ch = 0; ch < 16; ch++) {
        CP_WAIT0();
        __syncthreads();
        if (ch < 15) ISSUE(ch + 1);
        COMP(ch);
    }

    // Epilogue: descale (exact 2^-11), bias, BN (exact jax op order), fp32 out.
    {
        const int rb = m0 + wm + (lane >> 2);
        const int cb = n0 + wn + 2 * (lane & 3);
        float* Oz = OUT + zoff;
#pragma unroll
        for (int mt = 0; mt < 4; mt++) {
            int r0 = rb + mt * 16, r1 = r0 + 8;
            float g0 = gamma[r0], g1 = gamma[r1];
            float e0 = beta[r0],  e1 = beta[r1];
            float b0 = bias[r0],  b1 = bias[r1];
#pragma unroll
            for (int nt = 0; nt < 4; nt++) {
                int cc = cb + nt * 8;
                float* c = acc[mt][nt];
                float y0 = __fadd_rn(__fmul_rn(c[0], WSCALE_INV), b0);
                float y1 = __fadd_rn(__fmul_rn(c[1], WSCALE_INV), b0);
                float y2 = __fadd_rn(__fmul_rn(c[2], WSCALE_INV), b1);
                float y3 = __fadd_rn(__fmul_rn(c[3], WSCALE_INV), b1);
                y0 = __fadd_rn(__fmul_rn(__fmul_rn(g0, y0), inv), e0);
                y1 = __fadd_rn(__fmul_rn(__fmul_rn(g0, y1), inv), e0);
                y2 = __fadd_rn(__fmul_rn(__fmul_rn(g1, y2), inv), e1);
                y3 = __fadd_rn(__fmul_rn(__fmul_rn(g1, y3), inv), e1);
                *(float2*)(Oz + (size_t)r0 * N_ + cc) = make_float2(y0, y1);
                *(float2*)(Oz + (size_t)r1 * N_ + cc) = make_float2(y2, y3);
            }
        }
    }
}

// ============================================================================
// Multi-step LIF (R5-proven)
// ============================================================================
__global__ void lif_kernel(const float* __restrict__ in, float* __restrict__ out, float thr)
{
    size_t idx = (size_t)blockIdx.x * blockDim.x + threadIdx.x;
    if (idx >= PER_T) return;
    float v = 0.0f;
#pragma unroll
    for (int t = 0; t < T_; t++) {
        float x = in[(size_t)t * PER_T + idx];
        v = __fadd_rn(v, __fmul_rn(__fsub_rn(x, v), 0.5f));
        float s = (v >= thr) ? 1.0f : 0.0f;
        if (v >= thr) v = 0.0f;
        out[(size_t)t * PER_T + idx] = s;
    }
}

// ============================================================================
// kv via tensor cores, now with 2-stage cp.async staging.
// Same addresses/swizzle/MMA order as the R7-proven version.
// kv[d][e] = sum_n K[d][n] V[e][n] -> g_kvh[tbh][e][d] fp16 (counts, exact)
// ============================================================================
__global__ __launch_bounds__(256) void kv_mma()
{
    extern __shared__ char smem[];     // [2 stages][sK 16KB | sV 16KB] = 64KB
    const uint32_t sb = smem_u32(smem);

    const int tbh = blockIdx.x;
    const int tb = tbh >> 3, h = tbh & 7;
    const __half* K = gh_k + (size_t)tb * CN + (size_t)h * 64 * N_;
    const __half* V = gh_v + (size_t)tb * CN + (size_t)h * 64 * N_;

    const int tid = threadIdx.x;
    const int lane = tid & 31;
    const int w = tid >> 5;
    const int mt = (w & 3) * 16;
    const int nh = (w >> 2) * 32;

    float acc[4][4];
#pragma unroll
    for (int i = 0; i < 4; i++)
#pragma unroll
        for (int j = 0; j < 4; j++) acc[i][j] = 0.0f;

    // loader: half threads stage K, half stage V; 8 x 16B each per chunk
    const __half* src = (tid < 128) ? K : V;
    const uint32_t mofs = (tid < 128) ? 0u : 16384u;
    const int lt = tid & 127;

    auto ISSUE = [&](int c) {
        const uint32_t st = (uint32_t)(c & 1) * 32768u;
#pragma unroll
        for (int i = 0; i < 8; i++) {
            int idx = lt + i * 128;
            int row = idx >> 4, seg = idx & 15;
            int phys = seg ^ (row & 7);
            cp16(sb + st + mofs + (uint32_t)(row * 256 + phys * 16),
                 src + (size_t)row * N_ + c * 128 + seg * 8);
        }
        CP_COMMIT();
    };

    ISSUE(0);
#pragma unroll 1
    for (int c = 0; c < 8; c++) {
        CP_WAIT0();
        __syncthreads();
        if (c < 7) ISSUE(c + 1);

        const uint32_t skb = sb + (uint32_t)(c & 1) * 32768u;
        const uint32_t svb = skb + 16384u;
#pragma unroll
        for (int j = 0; j < 8; j++) {
            uint32_t a[4];
            {
                int row = mt + (lane & 7) + ((lane >> 3) & 1) * 8;
                int seg = 2 * j + (lane >> 4);
                ldmx4(a, skb + row * 256 + (seg ^ (row & 7)) * 16);
            }
#pragma unroll
            for (int p = 0; p < 2; p++) {
                uint32_t r[4];
                int row = nh + p * 16 + (lane & 7) + ((lane >> 4) & 1) * 8;
                int seg = 2 * j + ((lane >> 3) & 1);
                ldmx4(r, svb + row * 256 + (seg ^ (row & 7)) * 16);
                mma16(acc[2 * p],     a, &r[0]);
                mma16(acc[2 * p + 1], a, &r[2]);
            }
        }
    }

    __half* out = g_kvh + (size_t)tbh * 4096;
    const int d0 = mt + (lane >> 2);
    const int eb = nh + 2 * (lane & 3);
#pragma unroll
    for (int nt = 0; nt < 4; nt++) {
        int e = eb + nt * 8;
        out[(size_t)e * 64 + d0]           = __float2half_rn(acc[nt][0]);
        out[(size_t)(e + 1) * 64 + d0]     = __float2half_rn(acc[nt][1]);
        out[(size_t)e * 64 + d0 + 8]       = __float2half_rn(acc[nt][2]);
        out[(size_t)(e + 1) * 64 + d0 + 8] = __float2half_rn(acc[nt][3]);
    }
}

// ============================================================================
// av via tensor cores + fused attn-LIF (R7-proven, unchanged)
// ============================================================================
__global__ __launch_bounds__(256, 2) void av_lif_mma()
{
    __shared__ char sA[8192];
    __shared__ char sQ[32768];

    const int bh = blockIdx.y;
    const int b = bh >> 3, h = bh & 7;
    const int n0 = blockIdx.x * 128;

    const int tid = threadIdx.x;
    const int lane = tid & 31;
    const int w = tid >> 5;

    const uint32_t sab = smem_u32(sA);
    const uint32_t sqb = smem_u32(sQ);

    const int mrel = (lane & 7) + ((lane >> 3) & 1) * 8;
    const int hA = (lane >> 4) & 1;
    const int krel = (lane & 7) | (((lane >> 3) & 1) << 3);
    const int nrel = ((lane >> 4) & 1) * 8;
    const int nseg = (w * 16 + nrel) >> 3;

    float vst[4][2][4];
#pragma unroll
    for (int i = 0; i < 4; i++)
#pragma unroll
        for (int j = 0; j < 2; j++)
#pragma unroll
            for (int e = 0; e < 4; e++) vst[i][j][e] = 0.0f;

#pragma unroll 1
    for (int t = 0; t < 4; t++) {
        const int tb = t * 8 + b;
        const __half* KV = g_kvh + ((size_t)tb * 8 + h) * 4096;
        const __half* Q  = gh_q + (size_t)tb * CN + (size_t)h * 64 * N_;

        __syncthreads();
#pragma unroll
        for (int i = 0; i < 2; i++) {
            int idx = tid + i * 256;
            int e = idx >> 3, seg = idx & 7;
            int phys = seg ^ (e & 7);
            *(uint4*)(sA + e * 128 + phys * 16) =
                *(const uint4*)(KV + (size_t)e * 64 + seg * 8);
        }
#pragma unroll
        for (int i = 0; i < 4; i++) {
            int idx = tid + i * 256;
            int d = idx >> 4, seg = idx & 15;
            int phys = seg ^ (d & 7);
            *(uint4*)(sQ + d * 256 + phys * 16) =
                *(const uint4*)(Q + (size_t)d * N_ + n0 + seg * 8);
        }
        __syncthreads();

        float acc[4][2][4];
#pragma unroll
        for (int i = 0; i < 4; i++)
#pragma unroll
            for (int j = 0; j < 2; j++)
#pragma unroll
                for (int e = 0; e < 4; e++) acc[i][j][e] = 0.0f;

#pragma unroll
        for (int j = 0; j < 4; j++) {
            uint32_t bq[2][2];
            {
                uint32_t tr[4];
                int kr = j * 16 + krel;
                ldmx4t(tr, sqb + kr * 256 + ((nseg ^ (kr & 7))) * 16);
                bq[0][0] = tr[0]; bq[0][1] = tr[1];
                bq[1][0] = tr[2]; bq[1][1] = tr[3];
            }
#pragma unroll
            for (int mt = 0; mt < 4; mt++) {
                uint32_t a[4];
                int row = mt * 16 + mrel;
                int seg = 2 * j + hA;
                ldmx4(a, sab + row * 128 + ((seg ^ (row & 7))) * 16);
                mma16(acc[mt][0], a, bq[0]);
                mma16(acc[mt][1], a, bq[1]);
            }
        }

        __half* A = gh_a + (size_t)tb * CN + (size_t)h * 64 * N_;
        const int cb = n0 + w * 16 + 2 * (lane & 3);
#pragma unroll
        for (int mt = 0; mt < 4; mt++) {
            int e0 = mt * 16 + (lane >> 2), e1 = e0 + 8;
#pragma unroll
            for (int nt = 0; nt < 2; nt++) {
                int cc = cb + nt * 8;
                float* c = acc[mt][nt];
                float* vv = vst[mt][nt];
                float s0 = lif_step(vv[0], __fmul_rn(c[0], 0.125f), 0.5f);
                float s1 = lif_step(vv[1], __fmul_rn(c[1], 0.125f), 0.5f);
                float s2 = lif_step(vv[2], __fmul_rn(c[2], 0.125f), 0.5f);
                float s3 = lif_step(vv[3], __fmul_rn(c[3], 0.125f), 0.5f);
                *(uint32_t*)(A + (size_t)e0 * N_ + cc) =
                    packh(__float2half_rn(s0), __float2half_rn(s1));
                *(uint32_t*)(A + (size_t)e1 * N_ + cc) =
                    packh(__float2half_rn(s2), __float2half_rn(s3));
            }
        }
    }
}

// ============================================================================
extern "C" void kernel_launch(void* const* d_in, const int* in_sizes, int n_in,
                              void* d_out, int out_size)
{
    const float* x   = (const float*)d_in[0];
    const float* Wq  = (const float*)d_in[1];
    const float* qg  = (const float*)d_in[2];
    const float* qb  = (const float*)d_in[3];
    const float* Wk  = (const float*)d_in[4];
    const float* kg  = (const float*)d_in[5];
    const float* kb  = (const float*)d_in[6];
    const float* Wv  = (const float*)d_in[7];
    const float* vg  = (const float*)d_in[8];
    const float* vb  = (const float*)d_in[9];
    const float* Wp  = (const float*)d_in[10];
    const float* bp  = (const float*)d_in[11];
    const float* pg  = (const float*)d_in[12];
    const float* pb  = (const float*)d_in[13];
    float* out = (float*)d_out;

    __half *hq, *hk, *hv;
    float* p;
    cudaGetSymbolAddress((void**)&hq, gh_q);
    cudaGetSymbolAddress((void**)&hk, gh_k);
    cudaGetSymbolAddress((void**)&hv, gh_v);
    cudaGetSymbolAddress((void**)&p, g_p);

    float one_eps = 1.0f + 1e-5f;
    float inv = (float)(1.0 / sqrt((double)one_eps));

    const int SMEM_QKV = 32768 + 128 * 130 * 4;   // 99328, 2 CTA/SM (proven)
    const int SMEM_KV  = 65536;
    cudaFuncSetAttribute((const void*)gemm_lif_qkv,
                         cudaFuncAttributeMaxDynamicSharedMemorySize, SMEM_QKV);
    cudaFuncSetAttribute((const void*)kv_mma,
                         cudaFuncAttributeMaxDynamicSharedMemorySize, SMEM_KV);

    // one-shot pre-splits (identical arithmetic to the proven inline splits)
    split_w<<<4096, 256>>>(Wq, Wk, Wv, Wp);
    split_x<<<TBCN / 4 / 256, 256>>>(x);

    // merged q/k/v: 768 identical CTAs in one scheduling pool (R11-exact)
    gemm_lif_qkv<<<dim3(N_ / 128, C_ / 128, 24), 256, SMEM_QKV>>>(
        hq, hk, hv, qg, qb, kg, kb, vg, vb, inv);

    kv_mma<<<256, 256, SMEM_KV>>>();
    av_lif_mma<<<dim3(8, 64), 256>>>();

    // projection: K32 GEMM+BN (z=32), then standalone LIF (R11 shape)
    gemm_bn_p32<<<dim3(N_ / 128, C_ / 128, TB), 256>>>(p, pg, pb, bp, inv);
    lif_kernel<<<PER_T / 256, 256>>>(p, out, 1.0f);
}

// round 15
// speedup vs baseline: 1.0656x; 1.0045x over previous
#include <cuda_runtime.h>
#include <cuda_fp16.h>
#include <cmath>
#include <cstdint>

#define T_ 4
#define B_ 8
#define C_ 512
#define N_ 1024
#define TB 32
#define CN (C_*N_)          // 524288
#define TBCN (TB*CN)        // 16777216
#define PER_T (B_*CN)       // 4194304

// Scratch (static device globals — no runtime allocation)
__device__ __half gh_q[TBCN];        // q spikes fp16 (binary, exact)
__device__ __half gh_k[TBCN];
__device__ __half gh_v[TBCN];
__device__ __half gh_a[TBCN];        // attn spikes
__device__ __half g_kvh[TB*8*64*64]; // kv^T [tbh][e][d], counts <=1024, fp16-exact
__device__ float  g_p[TBCN];         // projection pre-LIF (BN output, fp32)
__device__ __half g_whi[4*C_*C_];    // W hi (x 2^11) for q,k,v,p
__device__ __half g_wlo[4*C_*C_];    // W lo
__device__ __half g_xhi[TBCN];       // x hi fp16 [z][c][n]
__device__ __half g_xlo[TBCN];       // x lo

#define WSCALE     2048.0f
#define WSCALE_INV 4.8828125e-4f     // 2^-11, exact

// ============================================================================
// helpers
// ============================================================================
__device__ __forceinline__ uint32_t smem_u32(const void* p) {
    uint32_t a;
    asm("{ .reg .u64 t; cvta.to.shared.u64 t, %1; cvt.u32.u64 %0, t; }" : "=r"(a) : "l"(p));
    return a;
}
__device__ __forceinline__ uint32_t packh(__half a, __half b) {
    __half2 h = __halves2half2(a, b);
    return *(uint32_t*)&h;
}
__device__ __forceinline__ void ldmx4(uint32_t* r, uint32_t addr) {
    asm volatile("ldmatrix.sync.aligned.m8n8.x4.shared.b16 {%0,%1,%2,%3}, [%4];"
                 : "=r"(r[0]), "=r"(r[1]), "=r"(r[2]), "=r"(r[3]) : "r"(addr));
}
__device__ __forceinline__ void ldmx4t(uint32_t* r, uint32_t addr) {
    asm volatile("ldmatrix.sync.aligned.m8n8.x4.trans.shared.b16 {%0,%1,%2,%3}, [%4];"
                 : "=r"(r[0]), "=r"(r[1]), "=r"(r[2]), "=r"(r[3]) : "r"(addr));
}
__device__ __forceinline__ void mma16(float* c, const uint32_t* a, const uint32_t* b) {
    asm volatile("mma.sync.aligned.m16n8k16.row.col.f32.f16.f16.f32 "
                 "{%0,%1,%2,%3}, {%4,%5,%6,%7}, {%8,%9}, {%0,%1,%2,%3};"
                 : "+f"(c[0]), "+f"(c[1]), "+f"(c[2]), "+f"(c[3])
                 : "r"(a[0]), "r"(a[1]), "r"(a[2]), "r"(a[3]), "r"(b[0]), "r"(b[1]));
}
__device__ __forceinline__ void cp16(uint32_t dst, const void* src) {
    asm volatile("cp.async.cg.shared.global [%0], [%1], 16;" :: "r"(dst), "l"(src) : "memory");
}
#define CP_COMMIT() asm volatile("cp.async.commit_group;" ::: "memory")
#define CP_WAIT0()  asm volatile("cp.async.wait_group 0;" ::: "memory")
#define CP_WAIT1()  asm volatile("cp.async.wait_group 1;" ::: "memory")

// exact reference LIF step: v' = v + (x - v)*0.5 ; spike >= thr ; hard reset
__device__ __forceinline__ float lif_step(float& vv, float x, float thr) {
    vv = __fadd_rn(vv, __fmul_rn(__fsub_rn(x, vv), 0.5f));
    float s = (vv >= thr) ? 1.0f : 0.0f;
    if (vv >= thr) vv = 0.0f;
    return s;
}

// ============================================================================
// Pre-split kernels (arithmetic identical to the proven inline splits)
// ============================================================================
__global__ void split_w(const float* __restrict__ w0, const float* __restrict__ w1,
                        const float* __restrict__ w2, const float* __restrict__ w3)
{
    int i = blockIdx.x * 256 + threadIdx.x;      // 0 .. 4*262144-1
    int which = i >> 18, off = i & 262143;
    const float* w = (which == 0) ? w0 : (which == 1) ? w1 : (which == 2) ? w2 : w3;
    float s = w[off] * WSCALE;
    __half hi = __float2half_rn(s);
    __half lo = __float2half_rn(s - __half2float(hi));
    g_whi[i] = hi;
    g_wlo[i] = lo;
}

__global__ void split_x(const float* __restrict__ x)
{
    size_t i4 = (size_t)blockIdx.x * 256 + threadIdx.x;   // 0 .. TBCN/4-1
    float4 v = *(const float4*)(x + i4 * 4);
    __half h0 = __float2half_rn(v.x), h1 = __float2half_rn(v.y);
    __half h2 = __float2half_rn(v.z), h3 = __float2half_rn(v.w);
    __half l0 = __float2half_rn(v.x - __half2float(h0));
    __half l1 = __float2half_rn(v.y - __half2float(h1));
    __half l2 = __float2half_rn(v.z - __half2float(h2));
    __half l3 = __float2half_rn(v.w - __half2float(h3));
    *(uint2*)(g_xhi + i4 * 4) = make_uint2(packh(h0, h1), packh(h2, h3));
    *(uint2*)(g_xlo + i4 * 4) = make_uint2(packh(l0, l1), packh(l2, l3));
}

// ============================================================================
// qkv GEMM + BN + multi-step LIF, 3-stage cp.async pipeline (wait_group 1),
// 2 CTA/SM guaranteed: panels 3x16KB = 49152, packed Vst 64KB -> 114688 B.
// M128 x N128, 8 warps of 64x32, K-chunk 16.
// Vst packed layout: Vst[cell*256 + tid], cell = (mt*4+nt)*4+e  (thread-owned,
// conflict-free, value-identical to the old padded layout).
// ============================================================================
__global__ __launch_bounds__(256, 2) void gemm_lif_qkv(
    __half* __restrict__ oq, __half* __restrict__ ok, __half* __restrict__ ov,
    const float* __restrict__ qg, const float* __restrict__ qb,
    const float* __restrict__ kg, const float* __restrict__ kb_,
    const float* __restrict__ vg, const float* __restrict__ vb,
    float inv)
{
    extern __shared__ char smbuf[];
    const uint32_t sbase = smem_u32(smbuf);
    float* Vst = (float*)(smbuf + 49152);

    const int z  = blockIdx.z;
    const int mi = z >> 3;
    const int b  = z & 7;
    const __half* Whi = g_whi + (size_t)mi * C_ * C_;
    const __half* Wlo = g_wlo + (size_t)mi * C_ * C_;
    __half* OUT    = (mi == 0) ? oq : (mi == 1) ? ok : ov;
    const float* gamma = (mi == 0) ? qg : (mi == 1) ? kg : vg;
    const float* beta  = (mi == 0) ? qb : (mi == 1) ? kb_ : vb;
    const int m0 = blockIdx.y * 128;
    const int n0 = blockIdx.x * 128;

    const int tid  = threadIdx.x;
    const int lane = tid & 31;
    const int wid  = tid >> 5;
    const int wm   = (wid >> 2) * 64;
    const int wn   = (wid & 3) * 32;

#pragma unroll
    for (int i = tid; i < 64 * 256; i += 256) Vst[i] = 0.0f;

    const int mA  = tid >> 1;
    const int kh8 = tid & 1;
    const __half* WhiRow = Whi + (size_t)(m0 + mA) * C_ + kh8 * 8;
    const __half* WloRow = Wlo + (size_t)(m0 + mA) * C_ + kh8 * 8;
    const uint32_t abyte = (uint32_t)((mA * 2 + (kh8 ^ ((mA >> 2) & 1))) * 16);
    const int kB  = tid >> 4;
    const int seg = tid & 15;
    const uint32_t bbyte = (uint32_t)(kB * 256 + ((seg ^ (kB & 7))) * 16);

    const int mrel = (lane & 7) | (((lane >> 3) & 1) << 3);
    const int hA   = (lane >> 4) & 1;
    uint32_t offA[4];
#pragma unroll
    for (int mt = 0; mt < 4; mt++) {
        int m = wm + mt * 16 + mrel;
        offA[mt] = (uint32_t)((m * 2 + (hA ^ ((m >> 2) & 1))) * 16);
    }
    const int krel = (lane & 7) | (((lane >> 3) & 1) << 3);
    const int nrel = ((lane >> 4) & 1) * 8;
    uint32_t offB[2];
#pragma unroll
    for (int p = 0; p < 2; p++) {
        int n = wn + p * 16 + nrel;
        offB[p] = (uint32_t)(krel * 256 + (((n >> 3) ^ (krel & 7))) * 16);
    }

    __syncthreads();

#pragma unroll 1
    for (int t = 0; t < 4; t++) {
        const size_t zoff = (size_t)(t * 8 + b) * CN;
        const __half* BhiBase = g_xhi + zoff + (size_t)kB * N_ + n0 + seg * 8;
        const __half* BloBase = g_xlo + zoff + (size_t)kB * N_ + n0 + seg * 8;

        float acc[4][4][4];
#pragma unroll
        for (int i = 0; i < 4; i++)
#pragma unroll
            for (int j = 0; j < 4; j++)
#pragma unroll
                for (int e = 0; e < 4; e++) acc[i][j][e] = 0.0f;

        auto ISSUE = [&](int ch) {
            const uint32_t st = (uint32_t)(ch % 3) * 16384u;
            const int kb = ch * 16;
            cp16(sbase + st + abyte,         WhiRow + kb);
            cp16(sbase + st + 4096 + abyte,  WloRow + kb);
            cp16(sbase + st + 8192 + bbyte,  BhiBase + (size_t)kb * N_);
            cp16(sbase + st + 12288 + bbyte, BloBase + (size_t)kb * N_);
            CP_COMMIT();
        };

        auto COMP = [&](int ch) {
            const uint32_t st = (uint32_t)(ch % 3) * 16384u;
            const uint32_t aHi = sbase + st;
            const uint32_t aLo = sbase + st + 4096;
            const uint32_t bHi = sbase + st + 8192;
            const uint32_t bLo = sbase + st + 12288;

            uint32_t ah[4][4], bh[4][2];
#pragma unroll
            for (int mt = 0; mt < 4; mt++) ldmx4(ah[mt], aHi + offA[mt]);
#pragma unroll
            for (int p = 0; p < 2; p++) {
                uint32_t tr[4];
                ldmx4t(tr, bHi + offB[p]);
                bh[2 * p][0] = tr[0]; bh[2 * p][1] = tr[1];
                bh[2 * p + 1][0] = tr[2]; bh[2 * p + 1][1] = tr[3];
            }
#pragma unroll
            for (int mt = 0; mt < 4; mt++)
#pragma unroll
                for (int nt = 0; nt < 4; nt++) mma16(acc[mt][nt], ah[mt], bh[nt]);
            {
                uint32_t bl[4][2];
#pragma unroll
                for (int p = 0; p < 2; p++) {
                    uint32_t tr[4];
                    ldmx4t(tr, bLo + offB[p]);
                    bl[2 * p][0] = tr[0]; bl[2 * p][1] = tr[1];
                    bl[2 * p + 1][0] = tr[2]; bl[2 * p + 1][1] = tr[3];
                }
#pragma unroll
                for (int mt = 0; mt < 4; mt++)
#pragma unroll
                    for (int nt = 0; nt < 4; nt++) mma16(acc[mt][nt], ah[mt], bl[nt]);
            }
#pragma unroll
            for (int mt = 0; mt < 4; mt++) ldmx4(ah[mt], aLo + offA[mt]);
#pragma unroll
            for (int mt = 0; mt < 4; mt++)
#pragma unroll
                for (int nt = 0; nt < 4; nt++) mma16(acc[mt][nt], ah[mt], bh[nt]);
        };

        // 3-stage: each chunk has two COMP epochs of load lead.
        ISSUE(0);
        ISSUE(1);
#pragma unroll 1
        for (int ch = 0; ch < 32; ch++) {
            if (ch == 31) { CP_WAIT0(); } else { CP_WAIT1(); }
            __syncthreads();                 // chunk ch visible; COMP(ch-1) retired
            if (ch < 30) ISSUE(ch + 2);      // buffer (ch+2)%3 == (ch-1)%3, retired
            COMP(ch);
        }
        __syncthreads();   // all COMP(31) reads done before next t's ISSUEs

        // Epilogue: descale, BN (exact jax op order), LIF (packed state in SMEM)
        {
            const int rb = m0 + wm + (lane >> 2);
            const int cb = n0 + wn + 2 * (lane & 3);
            __half* Oz = OUT + zoff;
#pragma unroll
            for (int mt = 0; mt < 4; mt++) {
                int r0 = rb + mt * 16, r1 = r0 + 8;
                float g0 = gamma[r0], g1 = gamma[r1];
                float e0 = beta[r0],  e1 = beta[r1];
#pragma unroll
                for (int nt = 0; nt < 4; nt++) {
                    int cc = cb + nt * 8;
                    float* c = acc[mt][nt];
                    float* vcell = &Vst[((mt * 4 + nt) * 4) * 256 + tid];
                    float y0 = __fmul_rn(c[0], WSCALE_INV);
                    float y1 = __fmul_rn(c[1], WSCALE_INV);
                    float y2 = __fmul_rn(c[2], WSCALE_INV);
                    float y3 = __fmul_rn(c[3], WSCALE_INV);
                    y0 = __fadd_rn(__fmul_rn(__fmul_rn(g0, y0), inv), e0);
                    y1 = __fadd_rn(__fmul_rn(__fmul_rn(g0, y1), inv), e0);
                    y2 = __fadd_rn(__fmul_rn(__fmul_rn(g1, y2), inv), e1);
                    y3 = __fadd_rn(__fmul_rn(__fmul_rn(g1, y3), inv), e1);
                    float vv0 = vcell[0], vv1 = vcell[256];
                    float vv2 = vcell[512], vv3 = vcell[768];
                    float s0 = lif_step(vv0, y0, 1.0f);
                    float s1 = lif_step(vv1, y1, 1.0f);
                    float s2 = lif_step(vv2, y2, 1.0f);
                    float s3 = lif_step(vv3, y3, 1.0f);
                    vcell[0] = vv0; vcell[256] = vv1;
                    vcell[512] = vv2; vcell[768] = vv3;
                    *(uint32_t*)(Oz + (size_t)r0 * N_ + cc) =
                        packh(__float2half_rn(s0), __float2half_rn(s1));
                    *(uint32_t*)(Oz + (size_t)r1 * N_ + cc) =
                        packh(__float2half_rn(s2), __float2half_rn(s3));
                }
            }
        }
    }
}

// ============================================================================
// Projection GEMM + BN, K-chunk 32 (R14-proven), unfused, binary fp16 B.
// ============================================================================
__global__ __launch_bounds__(256, 2) void gemm_bn_p32(
    float* __restrict__ OUT,
    const float* __restrict__ gamma, const float* __restrict__ beta,
    const float* __restrict__ bias, float inv)
{
    __shared__ char smbuf[49152];
    const uint32_t sbase = smem_u32(smbuf);

    const __half* Whi = g_whi + (size_t)3 * C_ * C_;
    const __half* Wlo = g_wlo + (size_t)3 * C_ * C_;
    const int z  = blockIdx.z;
    const int m0 = blockIdx.y * 128;
    const int n0 = blockIdx.x * 128;

    const int tid  = threadIdx.x;
    const int lane = tid & 31;
    const int wid  = tid >> 5;
    const int wm   = (wid >> 2) * 64;
    const int wn   = (wid & 3) * 32;

    const int mA  = tid >> 1;
    const int kh8 = tid & 1;
    const __half* WhiRow = Whi + (size_t)(m0 + mA) * C_ + kh8 * 8;
    const __half* WloRow = Wlo + (size_t)(m0 + mA) * C_ + kh8 * 8;
    const uint32_t abyte = (uint32_t)((mA * 2 + (kh8 ^ ((mA >> 2) & 1))) * 16);
    const int kB  = tid >> 4;
    const int seg = tid & 15;
    const uint32_t bbyte = (uint32_t)(kB * 256 + ((seg ^ (kB & 7))) * 16);

    const size_t zoff = (size_t)z * CN;
    const __half* BBase = gh_a + zoff + (size_t)kB * N_ + n0 + seg * 8;

    const int mrel = (lane & 7) | (((lane >> 3) & 1) << 3);
    const int hA   = (lane >> 4) & 1;
    uint32_t offA[4];
#pragma unroll
    for (int mt = 0; mt < 4; mt++) {
        int m = wm + mt * 16 + mrel;
        offA[mt] = (uint32_t)((m * 2 + (hA ^ ((m >> 2) & 1))) * 16);
    }
    const int krel = (lane & 7) | (((lane >> 3) & 1) << 3);
    const int nrel = ((lane >> 4) & 1) * 8;
    uint32_t offB[2];
#pragma unroll
    for (int p = 0; p < 2; p++) {
        int n = wn + p * 16 + nrel;
        offB[p] = (uint32_t)(krel * 256 + (((n >> 3) ^ (krel & 7))) * 16);
    }

    float acc[4][4][4];
#pragma unroll
    for (int i = 0; i < 4; i++)
#pragma unroll
        for (int j = 0; j < 4; j++)
#pragma unroll
            for (int e = 0; e < 4; e++) acc[i][j][e] = 0.0f;

    auto ISSUE = [&](int ch) {
        const uint32_t st = (uint32_t)(ch & 1) * 24576u;
        const int kb = ch * 32;
#pragma unroll
        for (int j = 0; j < 2; j++) {
            cp16(sbase + st + j * 4096 + abyte,          WhiRow + kb + j * 16);
            cp16(sbase + st + 8192 + j * 4096 + abyte,   WloRow + kb + j * 16);
            cp16(sbase + st + 16384 + j * 4096 + bbyte,  BBase + (size_t)(kb + j * 16) * N_);
        }
        CP_COMMIT();
    };

    auto COMP = [&](int ch) {
        const uint32_t st = (uint32_t)(ch & 1) * 24576u;
#pragma unroll
        for (int j = 0; j < 2; j++) {
            const uint32_t aHi = sbase + st + j * 4096;
            const uint32_t aLo = sbase + st + 8192 + j * 4096;
            const uint32_t bHi = sbase + st + 16384 + j * 4096;

            uint32_t ah[4][4], bh[4][2];
#pragma unroll
            for (int mt = 0; mt < 4; mt++) ldmx4(ah[mt], aHi + offA[mt]);
#pragma unroll
            for (int p = 0; p < 2; p++) {
                uint32_t tr[4];
                ldmx4t(tr, bHi + offB[p]);
                bh[2 * p][0] = tr[0]; bh[2 * p][1] = tr[1];
                bh[2 * p + 1][0] = tr[2]; bh[2 * p + 1][1] = tr[3];
            }
#pragma unroll
            for (int mt = 0; mt < 4; mt++)
#pragma unroll
                for (int nt = 0; nt < 4; nt++) mma16(acc[mt][nt], ah[mt], bh[nt]);
#pragma unroll
            for (int mt = 0; mt < 4; mt++) ldmx4(ah[mt], aLo + offA[mt]);
#pragma unroll
            for (int mt = 0; mt < 4; mt++)
#pragma unroll
                for (int nt = 0; nt < 4; nt++) mma16(acc[mt][nt], ah[mt], bh[nt]);
        }
    };

    ISSUE(0);
#pragma unroll 1
    for (int ch = 0; ch < 16; ch++) {
        CP_WAIT0();
        __syncthreads();
        if (ch < 15) ISSUE(ch + 1);
        COMP(ch);
    }

    {
        const int rb = m0 + wm + (lane >> 2);
        const int cb = n0 + wn + 2 * (lane & 3);
        float* Oz = OUT + zoff;
#pragma unroll
        for (int mt = 0; mt < 4; mt++) {
            int r0 = rb + mt * 16, r1 = r0 + 8;
            float g0 = gamma[r0], g1 = gamma[r1];
            float e0 = beta[r0],  e1 = beta[r1];
            float b0 = bias[r0],  b1 = bias[r1];
#pragma unroll
            for (int nt = 0; nt < 4; nt++) {
                int cc = cb + nt * 8;
                float* c = acc[mt][nt];
                float y0 = __fadd_rn(__fmul_rn(c[0], WSCALE_INV), b0);
                float y1 = __fadd_rn(__fmul_rn(c[1], WSCALE_INV), b0);
                float y2 = __fadd_rn(__fmul_rn(c[2], WSCALE_INV), b1);
                float y3 = __fadd_rn(__fmul_rn(c[3], WSCALE_INV), b1);
                y0 = __fadd_rn(__fmul_rn(__fmul_rn(g0, y0), inv), e0);
                y1 = __fadd_rn(__fmul_rn(__fmul_rn(g0, y1), inv), e0);
                y2 = __fadd_rn(__fmul_rn(__fmul_rn(g1, y2), inv), e1);
                y3 = __fadd_rn(__fmul_rn(__fmul_rn(g1, y3), inv), e1);
                *(float2*)(Oz + (size_t)r0 * N_ + cc) = make_float2(y0, y1);
                *(float2*)(Oz + (size_t)r1 * N_ + cc) = make_float2(y2, y3);
            }
        }
    }
}

// ============================================================================
// Multi-step LIF (R5-proven)
// ============================================================================
__global__ void lif_kernel(const float* __restrict__ in, float* __restrict__ out, float thr)
{
    size_t idx = (size_t)blockIdx.x * blockDim.x + threadIdx.x;
    if (idx >= PER_T) return;
    float v = 0.0f;
#pragma unroll
    for (int t = 0; t < T_; t++) {
        float x = in[(size_t)t * PER_T + idx];
        v = __fadd_rn(v, __fmul_rn(__fsub_rn(x, v), 0.5f));
        float s = (v >= thr) ? 1.0f : 0.0f;
        if (v >= thr) v = 0.0f;
        out[(size_t)t * PER_T + idx] = s;
    }
}

// ============================================================================
// kv via tensor cores, 2-stage cp.async (R14-proven)
// ============================================================================
__global__ __launch_bounds__(256) void kv_mma()
{
    extern __shared__ char smem[];     // [2 stages][sK 16KB | sV 16KB] = 64KB
    const uint32_t sb = smem_u32(smem);

    const int tbh = blockIdx.x;
    const int tb = tbh >> 3, h = tbh & 7;
    const __half* K = gh_k + (size_t)tb * CN + (size_t)h * 64 * N_;
    const __half* V = gh_v + (size_t)tb * CN + (size_t)h * 64 * N_;

    const int tid = threadIdx.x;
    const int lane = tid & 31;
    const int w = tid >> 5;
    const int mt = (w & 3) * 16;
    const int nh = (w >> 2) * 32;

    float acc[4][4];
#pragma unroll
    for (int i = 0; i < 4; i++)
#pragma unroll
        for (int j = 0; j < 4; j++) acc[i][j] = 0.0f;

    const __half* src = (tid < 128) ? K : V;
    const uint32_t mofs = (tid < 128) ? 0u : 16384u;
    const int lt = tid & 127;

    auto ISSUE = [&](int c) {
        const uint32_t st = (uint32_t)(c & 1) * 32768u;
#pragma unroll
        for (int i = 0; i < 8; i++) {
            int idx = lt + i * 128;
            int row = idx >> 4, seg = idx & 15;
            int phys = seg ^ (row & 7);
            cp16(sb + st + mofs + (uint32_t)(row * 256 + phys * 16),
                 src + (size_t)row * N_ + c * 128 + seg * 8);
        }
        CP_COMMIT();
    };

    ISSUE(0);
#pragma unroll 1
    for (int c = 0; c < 8; c++) {
        CP_WAIT0();
        __syncthreads();
        if (c < 7) ISSUE(c + 1);

        const uint32_t skb = sb + (uint32_t)(c & 1) * 32768u;
        const uint32_t svb = skb + 16384u;
#pragma unroll
        for (int j = 0; j < 8; j++) {
            uint32_t a[4];
            {
                int row = mt + (lane & 7) + ((lane >> 3) & 1) * 8;
                int seg = 2 * j + (lane >> 4);
                ldmx4(a, skb + row * 256 + (seg ^ (row & 7)) * 16);
            }
#pragma unroll
            for (int p = 0; p < 2; p++) {
                uint32_t r[4];
                int row = nh + p * 16 + (lane & 7) + ((lane >> 4) & 1) * 8;
                int seg = 2 * j + ((lane >> 3) & 1);
                ldmx4(r, svb + row * 256 + (seg ^ (row & 7)) * 16);
                mma16(acc[2 * p],     a, &r[0]);
                mma16(acc[2 * p + 1], a, &r[2]);
            }
        }
    }

    __half* out = g_kvh + (size_t)tbh * 4096;
    const int d0 = mt + (lane >> 2);
    const int eb = nh + 2 * (lane & 3);
#pragma unroll
    for (int nt = 0; nt < 4; nt++) {
        int e = eb + nt * 8;
        out[(size_t)e * 64 + d0]           = __float2half_rn(acc[nt][0]);
        out[(size_t)(e + 1) * 64 + d0]     = __float2half_rn(acc[nt][1]);
        out[(size_t)e * 64 + d0 + 8]       = __float2half_rn(acc[nt][2]);
        out[(size_t)(e + 1) * 64 + d0 + 8] = __float2half_rn(acc[nt][3]);
    }
}

// ============================================================================
// av via tensor cores + fused attn-LIF (R7-proven, unchanged)
// ============================================================================
__global__ __launch_bounds__(256, 2) void av_lif_mma()
{
    __shared__ char sA[8192];
    __shared__ char sQ[32768];

    const int bh = blockIdx.y;
    const int b = bh >> 3, h = bh & 7;
    const int n0 = blockIdx.x * 128;

    const int tid = threadIdx.x;
    const int lane = tid & 31;
    const int w = tid >> 5;

    const uint32_t sab = smem_u32(sA);
    const uint32_t sqb = smem_u32(sQ);

    const int mrel = (lane & 7) + ((lane >> 3) & 1) * 8;
    const int hA = (lane >> 4) & 1;
    const int krel = (lane & 7) | (((lane >> 3) & 1) << 3);
    const int nrel = ((lane >> 4) & 1) * 8;
    const int nseg = (w * 16 + nrel) >> 3;

    float vst[4][2][4];
#pragma unroll
    for (int i = 0; i < 4; i++)
#pragma unroll
        for (int j = 0; j < 2; j++)
#pragma unroll
            for (int e = 0; e < 4; e++) vst[i][j][e] = 0.0f;

#pragma unroll 1
    for (int t = 0; t < 4; t++) {
        const int tb = t * 8 + b;
        const __half* KV = g_kvh + ((size_t)tb * 8 + h) * 4096;
        const __half* Q  = gh_q + (size_t)tb * CN + (size_t)h * 64 * N_;

        __syncthreads();
#pragma unroll
        for (int i = 0; i < 2; i++) {
            int idx = tid + i * 256;
            int e = idx >> 3, seg = idx & 7;
            int phys = seg ^ (e & 7);
            *(uint4*)(sA + e * 128 + phys * 16) =
                *(const uint4*)(KV + (size_t)e * 64 + seg * 8);
        }
#pragma unroll
        for (int i = 0; i < 4; i++) {
            int idx = tid + i * 256;
            int d = idx >> 4, seg = idx & 15;
            int phys = seg ^ (d & 7);
            *(uint4*)(sQ + d * 256 + phys * 16) =
                *(const uint4*)(Q + (size_t)d * N_ + n0 + seg * 8);
        }
        __syncthreads();

        float acc[4][2][4];
#pragma unroll
        for (int i = 0; i < 4; i++)
#pragma unroll
            for (int j = 0; j < 2; j++)
#pragma unroll
                for (int e = 0; e < 4; e++) acc[i][j][e] = 0.0f;

#pragma unroll
        for (int j = 0; j < 4; j++) {
            uint32_t bq[2][2];
            {
                uint32_t tr[4];
                int kr = j * 16 + krel;
                ldmx4t(tr, sqb + kr * 256 + ((nseg ^ (kr & 7))) * 16);
                bq[0][0] = tr[0]; bq[0][1] = tr[1];
                bq[1][0] = tr[2]; bq[1][1] = tr[3];
            }
#pragma unroll
            for (int mt = 0; mt < 4; mt++) {
                uint32_t a[4];
                int row = mt * 16 + mrel;
                int seg = 2 * j + hA;
                ldmx4(a, sab + row * 128 + ((seg ^ (row & 7))) * 16);
                mma16(acc[mt][0], a, bq[0]);
                mma16(acc[mt][1], a, bq[1]);
            }
        }

        __half* A = gh_a + (size_t)tb * CN + (size_t)h * 64 * N_;
        const int cb = n0 + w * 16 + 2 * (lane & 3);
#pragma unroll
        for (int mt = 0; mt < 4; mt++) {
            int e0 = mt * 16 + (lane >> 2), e1 = e0 + 8;
#pragma unroll
            for (int nt = 0; nt < 2; nt++) {
                int cc = cb + nt * 8;
                float* c = acc[mt][nt];
                float* vv = vst[mt][nt];
                float s0 = lif_step(vv[0], __fmul_rn(c[0], 0.125f), 0.5f);
                float s1 = lif_step(vv[1], __fmul_rn(c[1], 0.125f), 0.5f);
                float s2 = lif_step(vv[2], __fmul_rn(c[2], 0.125f), 0.5f);
                float s3 = lif_step(vv[3], __fmul_rn(c[3], 0.125f), 0.5f);
                *(uint32_t*)(A + (size_t)e0 * N_ + cc) =
                    packh(__float2half_rn(s0), __float2half_rn(s1));
                *(uint32_t*)(A + (size_t)e1 * N_ + cc) =
                    packh(__float2half_rn(s2), __float2half_rn(s3));
            }
        }
    }
}

// ============================================================================
extern "C" void kernel_launch(void* const* d_in, const int* in_sizes, int n_in,
                              void* d_out, int out_size)
{
    const float* x   = (const float*)d_in[0];
    const float* Wq  = (const float*)d_in[1];
    const float* qg  = (const float*)d_in[2];
    const float* qb  = (const float*)d_in[3];
    const float* Wk  = (const float*)d_in[4];
    const float* kg  = (const float*)d_in[5];
    const float* kb  = (const float*)d_in[6];
    const float* Wv  = (const float*)d_in[7];
    const float* vg  = (const float*)d_in[8];
    const float* vb  = (const float*)d_in[9];
    const float* Wp  = (const float*)d_in[10];
    const float* bp  = (const float*)d_in[11];
    const float* pg  = (const float*)d_in[12];
    const float* pb  = (const float*)d_in[13];
    float* out = (float*)d_out;

    __half *hq, *hk, *hv;
    float* p;
    cudaGetSymbolAddress((void**)&hq, gh_q);
    cudaGetSymbolAddress((void**)&hk, gh_k);
    cudaGetSymbolAddress((void**)&hv, gh_v);
    cudaGetSymbolAddress((void**)&p, g_p);

    float one_eps = 1.0f + 1e-5f;
    float inv = (float)(1.0 / sqrt((double)one_eps));

    const int SMEM_QKV = 49152 + 65536;   // 114688 = 14 x 8KB -> 2 CTA/SM
    const int SMEM_KV  = 65536;
    cudaFuncSetAttribute((const void*)gemm_lif_qkv,
                         cudaFuncAttributeMaxDynamicSharedMemorySize, SMEM_QKV);
    cudaFuncSetAttribute((const void*)kv_mma,
                         cudaFuncAttributeMaxDynamicSharedMemorySize, SMEM_KV);

    // one-shot pre-splits (identical arithmetic to the proven inline splits)
    split_w<<<4096, 256>>>(Wq, Wk, Wv, Wp);
    split_x<<<TBCN / 4 / 256, 256>>>(x);

    // merged q/k/v: 768 identical CTAs in one scheduling pool
    gemm_lif_qkv<<<dim3(N_ / 128, C_ / 128, 24), 256, SMEM_QKV>>>(
        hq, hk, hv, qg, qb, kg, kb, vg, vb, inv);

    kv_mma<<<256, 256, SMEM_KV>>>();
    av_lif_mma<<<dim3(8, 64), 256>>>();

    // projection: K32 GEMM+BN (z=32), then standalone LIF (R14-proven)
    gemm_bn_p32<<<dim3(N_ / 128, C_ / 128, TB), 256>>>(p, pg, pb, bp, inv);
    lif_kernel<<<PER_T / 256, 256>>>(p, out, 1.0f);
}

// round 16
// speedup vs baseline: 1.0749x; 1.0087x over previous
#include <cuda_runtime.h>
#include <cuda_fp16.h>
#include <cmath>
#include <cstdint>

#define T_ 4
#define B_ 8
#define C_ 512
#define N_ 1024
#define TB 32
#define CN (C_*N_)          // 524288
#define TBCN (TB*CN)        // 16777216
#define PER_T (B_*CN)       // 4194304

// Scratch (static device globals — no runtime allocation)
__device__ __half gh_q[TBCN];        // q spikes fp16 (binary, exact)
__device__ __half gh_k[TBCN];
__device__ __half gh_v[TBCN];
__device__ __half gh_a[TBCN];        // attn spikes
__device__ __half g_kvh[TB*8*64*64]; // kv^T [tbh][e][d], counts <=1024, fp16-exact
__device__ float  g_p[TBCN];         // projection pre-LIF (BN output, fp32)
__device__ __half g_whi[4*C_*C_];    // W hi (x 2^11) for q,k,v,p
__device__ __half g_wlo[4*C_*C_];    // W lo
__device__ __half g_xhi[TBCN];       // x hi fp16 [z][c][n]
__device__ __half g_xlo[TBCN];       // x lo

#define WSCALE     2048.0f
#define WSCALE_INV 4.8828125e-4f     // 2^-11, exact

// ============================================================================
// helpers
// ============================================================================
__device__ __forceinline__ uint32_t smem_u32(const void* p) {
    uint32_t a;
    asm("{ .reg .u64 t; cvta.to.shared.u64 t, %1; cvt.u32.u64 %0, t; }" : "=r"(a) : "l"(p));
    return a;
}
__device__ __forceinline__ uint32_t packh(__half a, __half b) {
    __half2 h = __halves2half2(a, b);
    return *(uint32_t*)&h;
}
__device__ __forceinline__ void ldmx4(uint32_t* r, uint32_t addr) {
    asm volatile("ldmatrix.sync.aligned.m8n8.x4.shared.b16 {%0,%1,%2,%3}, [%4];"
                 : "=r"(r[0]), "=r"(r[1]), "=r"(r[2]), "=r"(r[3]) : "r"(addr));
}
__device__ __forceinline__ void ldmx4t(uint32_t* r, uint32_t addr) {
    asm volatile("ldmatrix.sync.aligned.m8n8.x4.trans.shared.b16 {%0,%1,%2,%3}, [%4];"
                 : "=r"(r[0]), "=r"(r[1]), "=r"(r[2]), "=r"(r[3]) : "r"(addr));
}
__device__ __forceinline__ void mma16(float* c, const uint32_t* a, const uint32_t* b) {
    asm volatile("mma.sync.aligned.m16n8k16.row.col.f32.f16.f16.f32 "
                 "{%0,%1,%2,%3}, {%4,%5,%6,%7}, {%8,%9}, {%0,%1,%2,%3};"
                 : "+f"(c[0]), "+f"(c[1]), "+f"(c[2]), "+f"(c[3])
                 : "r"(a[0]), "r"(a[1]), "r"(a[2]), "r"(a[3]), "r"(b[0]), "r"(b[1]));
}
__device__ __forceinline__ void cp16(uint32_t dst, const void* src) {
    asm volatile("cp.async.cg.shared.global [%0], [%1], 16;" :: "r"(dst), "l"(src) : "memory");
}
#define CP_COMMIT() asm volatile("cp.async.commit_group;" ::: "memory")
#define CP_WAIT0()  asm volatile("cp.async.wait_group 0;" ::: "memory")
#define CP_WAIT1()  asm volatile("cp.async.wait_group 1;" ::: "memory")

// exact reference LIF step: v' = v + (x - v)*0.5 ; spike >= thr ; hard reset
__device__ __forceinline__ float lif_step(float& vv, float x, float thr) {
    vv = __fadd_rn(vv, __fmul_rn(__fsub_rn(x, vv), 0.5f));
    float s = (vv >= thr) ? 1.0f : 0.0f;
    if (vv >= thr) vv = 0.0f;
    return s;
}

// ============================================================================
// Pre-split kernels (arithmetic identical to the proven inline splits)
// ============================================================================
__global__ void split_w(const float* __restrict__ w0, const float* __restrict__ w1,
                        const float* __restrict__ w2, const float* __restrict__ w3)
{
    int i = blockIdx.x * 256 + threadIdx.x;      // 0 .. 4*262144-1
    int which = i >> 18, off = i & 262143;
    const float* w = (which == 0) ? w0 : (which == 1) ? w1 : (which == 2) ? w2 : w3;
    float s = w[off] * WSCALE;
    __half hi = __float2half_rn(s);
    __half lo = __float2half_rn(s - __half2float(hi));
    g_whi[i] = hi;
    g_wlo[i] = lo;
}

__global__ void split_x(const float* __restrict__ x)
{
    size_t i4 = (size_t)blockIdx.x * 256 + threadIdx.x;   // 0 .. TBCN/4-1
    float4 v = *(const float4*)(x + i4 * 4);
    __half h0 = __float2half_rn(v.x), h1 = __float2half_rn(v.y);
    __half h2 = __float2half_rn(v.z), h3 = __float2half_rn(v.w);
    __half l0 = __float2half_rn(v.x - __half2float(h0));
    __half l1 = __float2half_rn(v.y - __half2float(h1));
    __half l2 = __float2half_rn(v.z - __half2float(h2));
    __half l3 = __float2half_rn(v.w - __half2float(h3));
    *(uint2*)(g_xhi + i4 * 4) = make_uint2(packh(h0, h1), packh(h2, h3));
    *(uint2*)(g_xlo + i4 * 4) = make_uint2(packh(l0, l1), packh(l2, l3));
}

// ============================================================================
// qkv GEMM + BN + multi-step LIF, 3-stage cp.async (R15-proven, unchanged).
// ============================================================================
__global__ __launch_bounds__(256, 2) void gemm_lif_qkv(
    __half* __restrict__ oq, __half* __restrict__ ok, __half* __restrict__ ov,
    const float* __restrict__ qg, const float* __restrict__ qb,
    const float* __restrict__ kg, const float* __restrict__ kb_,
    const float* __restrict__ vg, const float* __restrict__ vb,
    float inv)
{
    extern __shared__ char smbuf[];
    const uint32_t sbase = smem_u32(smbuf);
    float* Vst = (float*)(smbuf + 49152);

    const int z  = blockIdx.z;
    const int mi = z >> 3;
    const int b  = z & 7;
    const __half* Whi = g_whi + (size_t)mi * C_ * C_;
    const __half* Wlo = g_wlo + (size_t)mi * C_ * C_;
    __half* OUT    = (mi == 0) ? oq : (mi == 1) ? ok : ov;
    const float* gamma = (mi == 0) ? qg : (mi == 1) ? kg : vg;
    const float* beta  = (mi == 0) ? qb : (mi == 1) ? kb_ : vb;
    const int m0 = blockIdx.y * 128;
    const int n0 = blockIdx.x * 128;

    const int tid  = threadIdx.x;
    const int lane = tid & 31;
    const int wid  = tid >> 5;
    const int wm   = (wid >> 2) * 64;
    const int wn   = (wid & 3) * 32;

#pragma unroll
    for (int i = tid; i < 64 * 256; i += 256) Vst[i] = 0.0f;

    const int mA  = tid >> 1;
    const int kh8 = tid & 1;
    const __half* WhiRow = Whi + (size_t)(m0 + mA) * C_ + kh8 * 8;
    const __half* WloRow = Wlo + (size_t)(m0 + mA) * C_ + kh8 * 8;
    const uint32_t abyte = (uint32_t)((mA * 2 + (kh8 ^ ((mA >> 2) & 1))) * 16);
    const int kB  = tid >> 4;
    const int seg = tid & 15;
    const uint32_t bbyte = (uint32_t)(kB * 256 + ((seg ^ (kB & 7))) * 16);

    const int mrel = (lane & 7) | (((lane >> 3) & 1) << 3);
    const int hA   = (lane >> 4) & 1;
    uint32_t offA[4];
#pragma unroll
    for (int mt = 0; mt < 4; mt++) {
        int m = wm + mt * 16 + mrel;
        offA[mt] = (uint32_t)((m * 2 + (hA ^ ((m >> 2) & 1))) * 16);
    }
    const int krel = (lane & 7) | (((lane >> 3) & 1) << 3);
    const int nrel = ((lane >> 4) & 1) * 8;
    uint32_t offB[2];
#pragma unroll
    for (int p = 0; p < 2; p++) {
        int n = wn + p * 16 + nrel;
        offB[p] = (uint32_t)(krel * 256 + (((n >> 3) ^ (krel & 7))) * 16);
    }

    __syncthreads();

#pragma unroll 1
    for (int t = 0; t < 4; t++) {
        const size_t zoff = (size_t)(t * 8 + b) * CN;
        const __half* BhiBase = g_xhi + zoff + (size_t)kB * N_ + n0 + seg * 8;
        const __half* BloBase = g_xlo + zoff + (size_t)kB * N_ + n0 + seg * 8;

        float acc[4][4][4];
#pragma unroll
        for (int i = 0; i < 4; i++)
#pragma unroll
            for (int j = 0; j < 4; j++)
#pragma unroll
                for (int e = 0; e < 4; e++) acc[i][j][e] = 0.0f;

        auto ISSUE = [&](int ch) {
            const uint32_t st = (uint32_t)(ch % 3) * 16384u;
            const int kb = ch * 16;
            cp16(sbase + st + abyte,         WhiRow + kb);
            cp16(sbase + st + 4096 + abyte,  WloRow + kb);
            cp16(sbase + st + 8192 + bbyte,  BhiBase + (size_t)kb * N_);
            cp16(sbase + st + 12288 + bbyte, BloBase + (size_t)kb * N_);
            CP_COMMIT();
        };

        auto COMP = [&](int ch) {
            const uint32_t st = (uint32_t)(ch % 3) * 16384u;
            const uint32_t aHi = sbase + st;
            const uint32_t aLo = sbase + st + 4096;
            const uint32_t bHi = sbase + st + 8192;
            const uint32_t bLo = sbase + st + 12288;

            uint32_t ah[4][4], bh[4][2];
#pragma unroll
            for (int mt = 0; mt < 4; mt++) ldmx4(ah[mt], aHi + offA[mt]);
#pragma unroll
            for (int p = 0; p < 2; p++) {
                uint32_t tr[4];
                ldmx4t(tr, bHi + offB[p]);
                bh[2 * p][0] = tr[0]; bh[2 * p][1] = tr[1];
                bh[2 * p + 1][0] = tr[2]; bh[2 * p + 1][1] = tr[3];
            }
#pragma unroll
            for (int mt = 0; mt < 4; mt++)
#pragma unroll
                for (int nt = 0; nt < 4; nt++) mma16(acc[mt][nt], ah[mt], bh[nt]);
            {
                uint32_t bl[4][2];
#pragma unroll
                for (int p = 0; p < 2; p++) {
                    uint32_t tr[4];
                    ldmx4t(tr, bLo + offB[p]);
                    bl[2 * p][0] = tr[0]; bl[2 * p][1] = tr[1];
                    bl[2 * p + 1][0] = tr[2]; bl[2 * p + 1][1] = tr[3];
                }
#pragma unroll
                for (int mt = 0; mt < 4; mt++)
#pragma unroll
                    for (int nt = 0; nt < 4; nt++) mma16(acc[mt][nt], ah[mt], bl[nt]);
            }
#pragma unroll
            for (int mt = 0; mt < 4; mt++) ldmx4(ah[mt], aLo + offA[mt]);
#pragma unroll
            for (int mt = 0; mt < 4; mt++)
#pragma unroll
                for (int nt = 0; nt < 4; nt++) mma16(acc[mt][nt], ah[mt], bh[nt]);
        };

        ISSUE(0);
        ISSUE(1);
#pragma unroll 1
        for (int ch = 0; ch < 32; ch++) {
            if (ch == 31) { CP_WAIT0(); } else { CP_WAIT1(); }
            __syncthreads();
            if (ch < 30) ISSUE(ch + 2);
            COMP(ch);
        }
        __syncthreads();

        {
            const int rb = m0 + wm + (lane >> 2);
            const int cb = n0 + wn + 2 * (lane & 3);
            __half* Oz = OUT + zoff;
#pragma unroll
            for (int mt = 0; mt < 4; mt++) {
                int r0 = rb + mt * 16, r1 = r0 + 8;
                float g0 = gamma[r0], g1 = gamma[r1];
                float e0 = beta[r0],  e1 = beta[r1];
#pragma unroll
                for (int nt = 0; nt < 4; nt++) {
                    int cc = cb + nt * 8;
                    float* c = acc[mt][nt];
                    float* vcell = &Vst[((mt * 4 + nt) * 4) * 256 + tid];
                    float y0 = __fmul_rn(c[0], WSCALE_INV);
                    float y1 = __fmul_rn(c[1], WSCALE_INV);
                    float y2 = __fmul_rn(c[2], WSCALE_INV);
                    float y3 = __fmul_rn(c[3], WSCALE_INV);
                    y0 = __fadd_rn(__fmul_rn(__fmul_rn(g0, y0), inv), e0);
                    y1 = __fadd_rn(__fmul_rn(__fmul_rn(g0, y1), inv), e0);
                    y2 = __fadd_rn(__fmul_rn(__fmul_rn(g1, y2), inv), e1);
                    y3 = __fadd_rn(__fmul_rn(__fmul_rn(g1, y3), inv), e1);
                    float vv0 = vcell[0], vv1 = vcell[256];
                    float vv2 = vcell[512], vv3 = vcell[768];
                    float s0 = lif_step(vv0, y0, 1.0f);
                    float s1 = lif_step(vv1, y1, 1.0f);
                    float s2 = lif_step(vv2, y2, 1.0f);
                    float s3 = lif_step(vv3, y3, 1.0f);
                    vcell[0] = vv0; vcell[256] = vv1;
                    vcell[512] = vv2; vcell[768] = vv3;
                    *(uint32_t*)(Oz + (size_t)r0 * N_ + cc) =
                        packh(__float2half_rn(s0), __float2half_rn(s1));
                    *(uint32_t*)(Oz + (size_t)r1 * N_ + cc) =
                        packh(__float2half_rn(s2), __float2half_rn(s3));
                }
            }
        }
    }
}

// ============================================================================
// Projection GEMM + BN, K-chunk 32, now 3-stage cp.async (wait_group 1).
// Stage st @ (ch%3)*24576: Ah sub j @ j*4096, Al @8192+j*4096, Bh @16384+j*4096.
// Same MMA order as R14 -> bit-identical result. 72KB dynamic smem, 2 CTA/SM.
// ============================================================================
__global__ __launch_bounds__(256, 2) void gemm_bn_p32(
    float* __restrict__ OUT,
    const float* __restrict__ gamma, const float* __restrict__ beta,
    const float* __restrict__ bias, float inv)
{
    extern __shared__ char smbuf[];
    const uint32_t sbase = smem_u32(smbuf);

    const __half* Whi = g_whi + (size_t)3 * C_ * C_;
    const __half* Wlo = g_wlo + (size_t)3 * C_ * C_;
    const int z  = blockIdx.z;
    const int m0 = blockIdx.y * 128;
    const int n0 = blockIdx.x * 128;

    const int tid  = threadIdx.x;
    const int lane = tid & 31;
    const int wid  = tid >> 5;
    const int wm   = (wid >> 2) * 64;
    const int wn   = (wid & 3) * 32;

    const int mA  = tid >> 1;
    const int kh8 = tid & 1;
    const __half* WhiRow = Whi + (size_t)(m0 + mA) * C_ + kh8 * 8;
    const __half* WloRow = Wlo + (size_t)(m0 + mA) * C_ + kh8 * 8;
    const uint32_t abyte = (uint32_t)((mA * 2 + (kh8 ^ ((mA >> 2) & 1))) * 16);
    const int kB  = tid >> 4;
    const int seg = tid & 15;
    const uint32_t bbyte = (uint32_t)(kB * 256 + ((seg ^ (kB & 7))) * 16);

    const size_t zoff = (size_t)z * CN;
    const __half* BBase = gh_a + zoff + (size_t)kB * N_ + n0 + seg * 8;

    const int mrel = (lane & 7) | (((lane >> 3) & 1) << 3);
    const int hA   = (lane >> 4) & 1;
    uint32_t offA[4];
#pragma unroll
    for (int mt = 0; mt < 4; mt++) {
        int m = wm + mt * 16 + mrel;
        offA[mt] = (uint32_t)((m * 2 + (hA ^ ((m >> 2) & 1))) * 16);
    }
    const int krel = (lane & 7) | (((lane >> 3) & 1) << 3);
    const int nrel = ((lane >> 4) & 1) * 8;
    uint32_t offB[2];
#pragma unroll
    for (int p = 0; p < 2; p++) {
        int n = wn + p * 16 + nrel;
        offB[p] = (uint32_t)(krel * 256 + (((n >> 3) ^ (krel & 7))) * 16);
    }

    float acc[4][4][4];
#pragma unroll
    for (int i = 0; i < 4; i++)
#pragma unroll
        for (int j = 0; j < 4; j++)
#pragma unroll
            for (int e = 0; e < 4; e++) acc[i][j][e] = 0.0f;

    auto ISSUE = [&](int ch) {                 // ch = k32 chunk index (0..15)
        const uint32_t st = (uint32_t)(ch % 3) * 24576u;
        const int kb = ch * 32;
#pragma unroll
        for (int j = 0; j < 2; j++) {
            cp16(sbase + st + j * 4096 + abyte,          WhiRow + kb + j * 16);
            cp16(sbase + st + 8192 + j * 4096 + abyte,   WloRow + kb + j * 16);
            cp16(sbase + st + 16384 + j * 4096 + bbyte,  BBase + (size_t)(kb + j * 16) * N_);
        }
        CP_COMMIT();
    };

    auto COMP = [&](int ch) {
        const uint32_t st = (uint32_t)(ch % 3) * 24576u;
#pragma unroll
        for (int j = 0; j < 2; j++) {          // k16 sub-panels in k order
            const uint32_t aHi = sbase + st + j * 4096;
            const uint32_t aLo = sbase + st + 8192 + j * 4096;
            const uint32_t bHi = sbase + st + 16384 + j * 4096;

            uint32_t ah[4][4], bh[4][2];
#pragma unroll
            for (int mt = 0; mt < 4; mt++) ldmx4(ah[mt], aHi + offA[mt]);
#pragma unroll
            for (int p = 0; p < 2; p++) {
                uint32_t tr[4];
                ldmx4t(tr, bHi + offB[p]);
                bh[2 * p][0] = tr[0]; bh[2 * p][1] = tr[1];
                bh[2 * p + 1][0] = tr[2]; bh[2 * p + 1][1] = tr[3];
            }
#pragma unroll
            for (int mt = 0; mt < 4; mt++)
#pragma unroll
                for (int nt = 0; nt < 4; nt++) mma16(acc[mt][nt], ah[mt], bh[nt]);
#pragma unroll
            for (int mt = 0; mt < 4; mt++) ldmx4(ah[mt], aLo + offA[mt]);
#pragma unroll
            for (int mt = 0; mt < 4; mt++)
#pragma unroll
                for (int nt = 0; nt < 4; nt++) mma16(acc[mt][nt], ah[mt], bh[nt]);
        }
    };

    ISSUE(0);
    ISSUE(1);
#pragma unroll 1
    for (int ch = 0; ch < 16; ch++) {
        if (ch == 15) { CP_WAIT0(); } else { CP_WAIT1(); }
        __syncthreads();
        if (ch < 14) ISSUE(ch + 2);
        COMP(ch);
    }

    {
        const int rb = m0 + wm + (lane >> 2);
        const int cb = n0 + wn + 2 * (lane & 3);
        float* Oz = OUT + zoff;
#pragma unroll
        for (int mt = 0; mt < 4; mt++) {
            int r0 = rb + mt * 16, r1 = r0 + 8;
            float g0 = gamma[r0], g1 = gamma[r1];
            float e0 = beta[r0],  e1 = beta[r1];
            float b0 = bias[r0],  b1 = bias[r1];
#pragma unroll
            for (int nt = 0; nt < 4; nt++) {
                int cc = cb + nt * 8;
                float* c = acc[mt][nt];
                float y0 = __fadd_rn(__fmul_rn(c[0], WSCALE_INV), b0);
                float y1 = __fadd_rn(__fmul_rn(c[1], WSCALE_INV), b0);
                float y2 = __fadd_rn(__fmul_rn(c[2], WSCALE_INV), b1);
                float y3 = __fadd_rn(__fmul_rn(c[3], WSCALE_INV), b1);
                y0 = __fadd_rn(__fmul_rn(__fmul_rn(g0, y0), inv), e0);
                y1 = __fadd_rn(__fmul_rn(__fmul_rn(g0, y1), inv), e0);
                y2 = __fadd_rn(__fmul_rn(__fmul_rn(g1, y2), inv), e1);
                y3 = __fadd_rn(__fmul_rn(__fmul_rn(g1, y3), inv), e1);
                *(float2*)(Oz + (size_t)r0 * N_ + cc) = make_float2(y0, y1);
                *(float2*)(Oz + (size_t)r1 * N_ + cc) = make_float2(y2, y3);
            }
        }
    }
}

// ============================================================================
// Multi-step LIF (R5-proven)
// ============================================================================
__global__ void lif_kernel(const float* __restrict__ in, float* __restrict__ out, float thr)
{
    size_t idx = (size_t)blockIdx.x * blockDim.x + threadIdx.x;
    if (idx >= PER_T) return;
    float v = 0.0f;
#pragma unroll
    for (int t = 0; t < T_; t++) {
        float x = in[(size_t)t * PER_T + idx];
        v = __fadd_rn(v, __fmul_rn(__fsub_rn(x, v), 0.5f));
        float s = (v >= thr) ? 1.0f : 0.0f;
        if (v >= thr) v = 0.0f;
        out[(size_t)t * PER_T + idx] = s;
    }
}

// ============================================================================
// kv via tensor cores, 2-stage cp.async (R14-proven)
// ============================================================================
__global__ __launch_bounds__(256) void kv_mma()
{
    extern __shared__ char smem[];     // [2 stages][sK 16KB | sV 16KB] = 64KB
    const uint32_t sb = smem_u32(smem);

    const int tbh = blockIdx.x;
    const int tb = tbh >> 3, h = tbh & 7;
    const __half* K = gh_k + (size_t)tb * CN + (size_t)h * 64 * N_;
    const __half* V = gh_v + (size_t)tb * CN + (size_t)h * 64 * N_;

    const int tid = threadIdx.x;
    const int lane = tid & 31;
    const int w = tid >> 5;
    const int mt = (w & 3) * 16;
    const int nh = (w >> 2) * 32;

    float acc[4][4];
#pragma unroll
    for (int i = 0; i < 4; i++)
#pragma unroll
        for (int j = 0; j < 4; j++) acc[i][j] = 0.0f;

    const __half* src = (tid < 128) ? K : V;
    const uint32_t mofs = (tid < 128) ? 0u : 16384u;
    const int lt = tid & 127;

    auto ISSUE = [&](int c) {
        const uint32_t st = (uint32_t)(c & 1) * 32768u;
#pragma unroll
        for (int i = 0; i < 8; i++) {
            int idx = lt + i * 128;
            int row = idx >> 4, seg = idx & 15;
            int phys = seg ^ (row & 7);
            cp16(sb + st + mofs + (uint32_t)(row * 256 + phys * 16),
                 src + (size_t)row * N_ + c * 128 + seg * 8);
        }
        CP_COMMIT();
    };

    ISSUE(0);
#pragma unroll 1
    for (int c = 0; c < 8; c++) {
        CP_WAIT0();
        __syncthreads();
        if (c < 7) ISSUE(c + 1);

        const uint32_t skb = sb + (uint32_t)(c & 1) * 32768u;
        const uint32_t svb = skb + 16384u;
#pragma unroll
        for (int j = 0; j < 8; j++) {
            uint32_t a[4];
            {
                int row = mt + (lane & 7) + ((lane >> 3) & 1) * 8;
                int seg = 2 * j + (lane >> 4);
                ldmx4(a, skb + row * 256 + (seg ^ (row & 7)) * 16);
            }
#pragma unroll
            for (int p = 0; p < 2; p++) {
                uint32_t r[4];
                int row = nh + p * 16 + (lane & 7) + ((lane >> 4) & 1) * 8;
                int seg = 2 * j + ((lane >> 3) & 1);
                ldmx4(r, svb + row * 256 + (seg ^ (row & 7)) * 16);
                mma16(acc[2 * p],     a, &r[0]);
                mma16(acc[2 * p + 1], a, &r[2]);
            }
        }
    }

    __half* out = g_kvh + (size_t)tbh * 4096;
    const int d0 = mt + (lane >> 2);
    const int eb = nh + 2 * (lane & 3);
#pragma unroll
    for (int nt = 0; nt < 4; nt++) {
        int e = eb + nt * 8;
        out[(size_t)e * 64 + d0]           = __float2half_rn(acc[nt][0]);
        out[(size_t)(e + 1) * 64 + d0]     = __float2half_rn(acc[nt][1]);
        out[(size_t)e * 64 + d0 + 8]       = __float2half_rn(acc[nt][2]);
        out[(size_t)(e + 1) * 64 + d0 + 8] = __float2half_rn(acc[nt][3]);
    }
}

// ============================================================================
// av via tensor cores + fused attn-LIF, now with 2-stage cp.async across t.
// Same destination bytes/swizzle/MMA order as the R7-proven version.
// Stage st @ (t&1)*40960: sA (kvT) @0 (8KB), sQ @8192 (32KB).
// ============================================================================
__global__ __launch_bounds__(256, 2) void av_lif_mma()
{
    extern __shared__ char smem[];     // 2 x 40960 = 81920 B
    const uint32_t sb = smem_u32(smem);

    const int bh = blockIdx.y;
    const int b = bh >> 3, h = bh & 7;
    const int n0 = blockIdx.x * 128;

    const int tid = threadIdx.x;
    const int lane = tid & 31;
    const int w = tid >> 5;

    const int mrel = (lane & 7) + ((lane >> 3) & 1) * 8;
    const int hA = (lane >> 4) & 1;
    const int krel = (lane & 7) | (((lane >> 3) & 1) << 3);
    const int nrel = ((lane >> 4) & 1) * 8;
    const int nseg = (w * 16 + nrel) >> 3;

    float vst[4][2][4];
#pragma unroll
    for (int i = 0; i < 4; i++)
#pragma unroll
        for (int j = 0; j < 2; j++)
#pragma unroll
            for (int e = 0; e < 4; e++) vst[i][j][e] = 0.0f;

    auto ISSUE = [&](int t) {
        const int tb = t * 8 + b;
        const __half* KV = g_kvh + ((size_t)tb * 8 + h) * 4096;
        const __half* Q  = gh_q + (size_t)tb * CN + (size_t)h * 64 * N_;
        const uint32_t st = (uint32_t)(t & 1) * 40960u;
        // kvT: 512 x 16B, 2 per thread
#pragma unroll
        for (int i = 0; i < 2; i++) {
            int idx = tid + i * 256;
            int e = idx >> 3, seg = idx & 7;
            int phys = seg ^ (e & 7);
            cp16(sb + st + (uint32_t)(e * 128 + phys * 16),
                 KV + (size_t)e * 64 + seg * 8);
        }
        // Q chunk: 1024 x 16B, 4 per thread
#pragma unroll
        for (int i = 0; i < 4; i++) {
            int idx = tid + i * 256;
            int d = idx >> 4, seg = idx & 15;
            int phys = seg ^ (d & 7);
            cp16(sb + st + 8192u + (uint32_t)(d * 256 + phys * 16),
                 Q + (size_t)d * N_ + n0 + seg * 8);
        }
        CP_COMMIT();
    };

    ISSUE(0);
#pragma unroll 1
    for (int t = 0; t < 4; t++) {
        CP_WAIT0();
        __syncthreads();
        if (t < 3) ISSUE(t + 1);

        const uint32_t sab = sb + (uint32_t)(t & 1) * 40960u;
        const uint32_t sqb = sab + 8192u;

        float acc[4][2][4];
#pragma unroll
        for (int i = 0; i < 4; i++)
#pragma unroll
            for (int j = 0; j < 2; j++)
#pragma unroll
                for (int e = 0; e < 4; e++) acc[i][j][e] = 0.0f;

#pragma unroll
        for (int j = 0; j < 4; j++) {
            uint32_t bq[2][2];
            {
                uint32_t tr[4];
                int kr = j * 16 + krel;
                ldmx4t(tr, sqb + kr * 256 + ((nseg ^ (kr & 7))) * 16);
                bq[0][0] = tr[0]; bq[0][1] = tr[1];
                bq[1][0] = tr[2]; bq[1][1] = tr[3];
            }
#pragma unroll
            for (int mt = 0; mt < 4; mt++) {
                uint32_t a[4];
                int row = mt * 16 + mrel;
                int seg = 2 * j + hA;
                ldmx4(a, sab + row * 128 + ((seg ^ (row & 7))) * 16);
                mma16(acc[mt][0], a, bq[0]);
                mma16(acc[mt][1], a, bq[1]);
            }
        }

        const int tb = t * 8 + b;
        __half* A = gh_a + (size_t)tb * CN + (size_t)h * 64 * N_;
        const int cb = n0 + w * 16 + 2 * (lane & 3);
#pragma unroll
        for (int mt = 0; mt < 4; mt++) {
            int e0 = mt * 16 + (lane >> 2), e1 = e0 + 8;
#pragma unroll
            for (int nt = 0; nt < 2; nt++) {
                int cc = cb + nt * 8;
                float* c = acc[mt][nt];
                float* vv = vst[mt][nt];
                float s0 = lif_step(vv[0], __fmul_rn(c[0], 0.125f), 0.5f);
                float s1 = lif_step(vv[1], __fmul_rn(c[1], 0.125f), 0.5f);
                float s2 = lif_step(vv[2], __fmul_rn(c[2], 0.125f), 0.5f);
                float s3 = lif_step(vv[3], __fmul_rn(c[3], 0.125f), 0.5f);
                *(uint32_t*)(A + (size_t)e0 * N_ + cc) =
                    packh(__float2half_rn(s0), __float2half_rn(s1));
                *(uint32_t*)(A + (size_t)e1 * N_ + cc) =
                    packh(__float2half_rn(s2), __float2half_rn(s3));
            }
        }
    }
}

// ============================================================================
extern "C" void kernel_launch(void* const* d_in, const int* in_sizes, int n_in,
                              void* d_out, int out_size)
{
    const float* x   = (const float*)d_in[0];
    const float* Wq  = (const float*)d_in[1];
    const float* qg  = (const float*)d_in[2];
    const float* qb  = (const float*)d_in[3];
    const float* Wk  = (const float*)d_in[4];
    const float* kg  = (const float*)d_in[5];
    const float* kb  = (const float*)d_in[6];
    const float* Wv  = (const float*)d_in[7];
    const float* vg  = (const float*)d_in[8];
    const float* vb  = (const float*)d_in[9];
    const float* Wp  = (const float*)d_in[10];
    const float* bp  = (const float*)d_in[11];
    const float* pg  = (const float*)d_in[12];
    const float* pb  = (const float*)d_in[13];
    float* out = (float*)d_out;

    __half *hq, *hk, *hv;
    float* p;
    cudaGetSymbolAddress((void**)&hq, gh_q);
    cudaGetSymbolAddress((void**)&hk, gh_k);
    cudaGetSymbolAddress((void**)&hv, gh_v);
    cudaGetSymbolAddress((void**)&p, g_p);

    float one_eps = 1.0f + 1e-5f;
    float inv = (float)(1.0 / sqrt((double)one_eps));

    const int SMEM_QKV = 49152 + 65536;   // 114688 -> 2 CTA/SM (R15-proven)
    const int SMEM_KV  = 65536;
    const int SMEM_P   = 73728;           // 3 x 24KB -> 2 CTA/SM
    const int SMEM_AV  = 81920;           // 2 x 40KB -> 2 CTA/SM
    cudaFuncSetAttribute((const void*)gemm_lif_qkv,
                         cudaFuncAttributeMaxDynamicSharedMemorySize, SMEM_QKV);
    cudaFuncSetAttribute((const void*)kv_mma,
                         cudaFuncAttributeMaxDynamicSharedMemorySize, SMEM_KV);
    cudaFuncSetAttribute((const void*)gemm_bn_p32,
                         cudaFuncAttributeMaxDynamicSharedMemorySize, SMEM_P);
    cudaFuncSetAttribute((const void*)av_lif_mma,
                         cudaFuncAttributeMaxDynamicSharedMemorySize, SMEM_AV);

    // one-shot pre-splits (identical arithmetic to the proven inline splits)
    split_w<<<4096, 256>>>(Wq, Wk, Wv, Wp);
    split_x<<<TBCN / 4 / 256, 256>>>(x);

    // merged q/k/v: 768 identical CTAs in one scheduling pool
    gemm_lif_qkv<<<dim3(N_ / 128, C_ / 128, 24), 256, SMEM_QKV>>>(
        hq, hk, hv, qg, qb, kg, kb, vg, vb, inv);

    kv_mma<<<256, 256, SMEM_KV>>>();
    av_lif_mma<<<dim3(8, 64), 256, SMEM_AV>>>();

    // projection: K32 3-stage GEMM+BN (z=32), then standalone LIF
    gemm_bn_p32<<<dim3(N_ / 128, C_ / 128, TB), 256, SMEM_P>>>(p, pg, pb, bp, inv);
    lif_kernel<<<PER_T / 256, 256>>>(p, out, 1.0f);
}

// round 17
// speedup vs baseline: 1.0880x; 1.0122x over previous
#include <cuda_runtime.h>
#include <cuda_fp16.h>
#include <cmath>
#include <cstdint>

#define T_ 4
#define B_ 8
#define C_ 512
#define N_ 1024
#define TB 32
#define CN (C_*N_)          // 524288
#define TBCN (TB*CN)        // 16777216
#define PER_T (B_*CN)       // 4194304

// Scratch (static device globals — no runtime allocation)
__device__ __half gh_q[TBCN];        // q spikes fp16 (binary, exact)
__device__ __half gh_k[TBCN];
__device__ __half gh_v[TBCN];
__device__ __half gh_a[TBCN];        // attn spikes
__device__ __half g_kvh[TB*8*64*64]; // kv^T [tbh][e][d], counts <=1024, fp16-exact
__device__ float  g_p[TBCN];         // projection pre-LIF (BN output, fp32)
__device__ __half g_whi[4*C_*C_];    // W hi (x 2^11) for q,k,v,p
__device__ __half g_wlo[4*C_*C_];    // W lo
__device__ __half g_xhi[TBCN];       // x hi fp16 [z][c][n]
__device__ __half g_xlo[TBCN];       // x lo

#define WSCALE     2048.0f
#define WSCALE_INV 4.8828125e-4f     // 2^-11, exact

// ============================================================================
// helpers
// ============================================================================
__device__ __forceinline__ uint32_t smem_u32(const void* p) {
    uint32_t a;
    asm("{ .reg .u64 t; cvta.to.shared.u64 t, %1; cvt.u32.u64 %0, t; }" : "=r"(a) : "l"(p));
    return a;
}
__device__ __forceinline__ uint32_t packh(__half a, __half b) {
    __half2 h = __halves2half2(a, b);
    return *(uint32_t*)&h;
}
__device__ __forceinline__ void ldmx4(uint32_t* r, uint32_t addr) {
    asm volatile("ldmatrix.sync.aligned.m8n8.x4.shared.b16 {%0,%1,%2,%3}, [%4];"
                 : "=r"(r[0]), "=r"(r[1]), "=r"(r[2]), "=r"(r[3]) : "r"(addr));
}
__device__ __forceinline__ void ldmx4t(uint32_t* r, uint32_t addr) {
    asm volatile("ldmatrix.sync.aligned.m8n8.x4.trans.shared.b16 {%0,%1,%2,%3}, [%4];"
                 : "=r"(r[0]), "=r"(r[1]), "=r"(r[2]), "=r"(r[3]) : "r"(addr));
}
__device__ __forceinline__ void mma16(float* c, const uint32_t* a, const uint32_t* b) {
    asm volatile("mma.sync.aligned.m16n8k16.row.col.f32.f16.f16.f32 "
                 "{%0,%1,%2,%3}, {%4,%5,%6,%7}, {%8,%9}, {%0,%1,%2,%3};"
                 : "+f"(c[0]), "+f"(c[1]), "+f"(c[2]), "+f"(c[3])
                 : "r"(a[0]), "r"(a[1]), "r"(a[2]), "r"(a[3]), "r"(b[0]), "r"(b[1]));
}
__device__ __forceinline__ void cp16(uint32_t dst, const void* src) {
    asm volatile("cp.async.cg.shared.global [%0], [%1], 16;" :: "r"(dst), "l"(src) : "memory");
}
#define CP_COMMIT() asm volatile("cp.async.commit_group;" ::: "memory")
#define CP_WAIT0()  asm volatile("cp.async.wait_group 0;" ::: "memory")
#define CP_WAIT1()  asm volatile("cp.async.wait_group 1;" ::: "memory")

// exact reference LIF step: v' = v + (x - v)*0.5 ; spike >= thr ; hard reset
__device__ __forceinline__ float lif_step(float& vv, float x, float thr) {
    vv = __fadd_rn(vv, __fmul_rn(__fsub_rn(x, vv), 0.5f));
    float s = (vv >= thr) ? 1.0f : 0.0f;
    if (vv >= thr) vv = 0.0f;
    return s;
}

// ============================================================================
// Merged pre-split kernel: blocks [0, XB) split x (float4/thread);
// blocks [XB, XB+WB) split the 4 weight matrices (float4/thread).
// Arithmetic identical to the proven separate kernels.
// ============================================================================
#define XB_BLOCKS (TBCN / 4 / 256)        // 16384
#define WB_BLOCKS (4 * C_ * C_ / 4 / 256) // 1024

__global__ void split_all(const float* __restrict__ x,
                          const float* __restrict__ w0, const float* __restrict__ w1,
                          const float* __restrict__ w2, const float* __restrict__ w3)
{
    int blk = blockIdx.x;
    if (blk < XB_BLOCKS) {
        size_t i4 = (size_t)blk * 256 + threadIdx.x;
        float4 v = *(const float4*)(x + i4 * 4);
        __half h0 = __float2half_rn(v.x), h1 = __float2half_rn(v.y);
        __half h2 = __float2half_rn(v.z), h3 = __float2half_rn(v.w);
        __half l0 = __float2half_rn(v.x - __half2float(h0));
        __half l1 = __float2half_rn(v.y - __half2float(h1));
        __half l2 = __float2half_rn(v.z - __half2float(h2));
        __half l3 = __float2half_rn(v.w - __half2float(h3));
        *(uint2*)(g_xhi + i4 * 4) = make_uint2(packh(h0, h1), packh(h2, h3));
        *(uint2*)(g_xlo + i4 * 4) = make_uint2(packh(l0, l1), packh(l2, l3));
    } else {
        int i4 = (blk - XB_BLOCKS) * 256 + threadIdx.x;   // float4 index, 0..262143
        int which = i4 >> 16;                              // 65536 float4 per matrix
        int off4 = i4 & 65535;
        const float* w = (which == 0) ? w0 : (which == 1) ? w1 : (which == 2) ? w2 : w3;
        float4 v = *(const float4*)(w + (size_t)off4 * 4);
        float s0 = v.x * WSCALE, s1 = v.y * WSCALE;
        float s2 = v.z * WSCALE, s3 = v.w * WSCALE;
        __half h0 = __float2half_rn(s0), h1 = __float2half_rn(s1);
        __half h2 = __float2half_rn(s2), h3 = __float2half_rn(s3);
        __half l0 = __float2half_rn(s0 - __half2float(h0));
        __half l1 = __float2half_rn(s1 - __half2float(h1));
        __half l2 = __float2half_rn(s2 - __half2float(h2));
        __half l3 = __float2half_rn(s3 - __half2float(h3));
        *(uint2*)(g_whi + (size_t)i4 * 4) = make_uint2(packh(h0, h1), packh(h2, h3));
        *(uint2*)(g_wlo + (size_t)i4 * 4) = make_uint2(packh(l0, l1), packh(l2, l3));
    }
}

// ============================================================================
// qkv GEMM + BN + multi-step LIF, 3-stage cp.async (R15/R16-proven, unchanged).
// ============================================================================
__global__ __launch_bounds__(256, 2) void gemm_lif_qkv(
    __half* __restrict__ oq, __half* __restrict__ ok, __half* __restrict__ ov,
    const float* __restrict__ qg, const float* __restrict__ qb,
    const float* __restrict__ kg, const float* __restrict__ kb_,
    const float* __restrict__ vg, const float* __restrict__ vb,
    float inv)
{
    extern __shared__ char smbuf[];
    const uint32_t sbase = smem_u32(smbuf);
    float* Vst = (float*)(smbuf + 49152);

    const int z  = blockIdx.z;
    const int mi = z >> 3;
    const int b  = z & 7;
    const __half* Whi = g_whi + (size_t)mi * C_ * C_;
    const __half* Wlo = g_wlo + (size_t)mi * C_ * C_;
    __half* OUT    = (mi == 0) ? oq : (mi == 1) ? ok : ov;
    const float* gamma = (mi == 0) ? qg : (mi == 1) ? kg : vg;
    const float* beta  = (mi == 0) ? qb : (mi == 1) ? kb_ : vb;
    const int m0 = blockIdx.y * 128;
    const int n0 = blockIdx.x * 128;

    const int tid  = threadIdx.x;
    const int lane = tid & 31;
    const int wid  = tid >> 5;
    const int wm   = (wid >> 2) * 64;
    const int wn   = (wid & 3) * 32;

#pragma unroll
    for (int i = tid; i < 64 * 256; i += 256) Vst[i] = 0.0f;

    const int mA  = tid >> 1;
    const int kh8 = tid & 1;
    const __half* WhiRow = Whi + (size_t)(m0 + mA) * C_ + kh8 * 8;
    const __half* WloRow = Wlo + (size_t)(m0 + mA) * C_ + kh8 * 8;
    const uint32_t abyte = (uint32_t)((mA * 2 + (kh8 ^ ((mA >> 2) & 1))) * 16);
    const int kB  = tid >> 4;
    const int seg = tid & 15;
    const uint32_t bbyte = (uint32_t)(kB * 256 + ((seg ^ (kB & 7))) * 16);

    const int mrel = (lane & 7) | (((lane >> 3) & 1) << 3);
    const int hA   = (lane >> 4) & 1;
    uint32_t offA[4];
#pragma unroll
    for (int mt = 0; mt < 4; mt++) {
        int m = wm + mt * 16 + mrel;
        offA[mt] = (uint32_t)((m * 2 + (hA ^ ((m >> 2) & 1))) * 16);
    }
    const int krel = (lane & 7) | (((lane >> 3) & 1) << 3);
    const int nrel = ((lane >> 4) & 1) * 8;
    uint32_t offB[2];
#pragma unroll
    for (int p = 0; p < 2; p++) {
        int n = wn + p * 16 + nrel;
        offB[p] = (uint32_t)(krel * 256 + (((n >> 3) ^ (krel & 7))) * 16);
    }

    __syncthreads();

#pragma unroll 1
    for (int t = 0; t < 4; t++) {
        const size_t zoff = (size_t)(t * 8 + b) * CN;
        const __half* BhiBase = g_xhi + zoff + (size_t)kB * N_ + n0 + seg * 8;
        const __half* BloBase = g_xlo + zoff + (size_t)kB * N_ + n0 + seg * 8;

        float acc[4][4][4];
#pragma unroll
        for (int i = 0; i < 4; i++)
#pragma unroll
            for (int j = 0; j < 4; j++)
#pragma unroll
                for (int e = 0; e < 4; e++) acc[i][j][e] = 0.0f;

        auto ISSUE = [&](int ch) {
            const uint32_t st = (uint32_t)(ch % 3) * 16384u;
            const int kb = ch * 16;
            cp16(sbase + st + abyte,         WhiRow + kb);
            cp16(sbase + st + 4096 + abyte,  WloRow + kb);
            cp16(sbase + st + 8192 + bbyte,  BhiBase + (size_t)kb * N_);
            cp16(sbase + st + 12288 + bbyte, BloBase + (size_t)kb * N_);
            CP_COMMIT();
        };

        auto COMP = [&](int ch) {
            const uint32_t st = (uint32_t)(ch % 3) * 16384u;
            const uint32_t aHi = sbase + st;
            const uint32_t aLo = sbase + st + 4096;
            const uint32_t bHi = sbase + st + 8192;
            const uint32_t bLo = sbase + st + 12288;

            uint32_t ah[4][4], bh[4][2];
#pragma unroll
            for (int mt = 0; mt < 4; mt++) ldmx4(ah[mt], aHi + offA[mt]);
#pragma unroll
            for (int p = 0; p < 2; p++) {
                uint32_t tr[4];
                ldmx4t(tr, bHi + offB[p]);
                bh[2 * p][0] = tr[0]; bh[2 * p][1] = tr[1];
                bh[2 * p + 1][0] = tr[2]; bh[2 * p + 1][1] = tr[3];
            }
#pragma unroll
            for (int mt = 0; mt < 4; mt++)
#pragma unroll
                for (int nt = 0; nt < 4; nt++) mma16(acc[mt][nt], ah[mt], bh[nt]);
            {
                uint32_t bl[4][2];
#pragma unroll
                for (int p = 0; p < 2; p++) {
                    uint32_t tr[4];
                    ldmx4t(tr, bLo + offB[p]);
                    bl[2 * p][0] = tr[0]; bl[2 * p][1] = tr[1];
                    bl[2 * p + 1][0] = tr[2]; bl[2 * p + 1][1] = tr[3];
                }
#pragma unroll
                for (int mt = 0; mt < 4; mt++)
#pragma unroll
                    for (int nt = 0; nt < 4; nt++) mma16(acc[mt][nt], ah[mt], bl[nt]);
            }
#pragma unroll
            for (int mt = 0; mt < 4; mt++) ldmx4(ah[mt], aLo + offA[mt]);
#pragma unroll
            for (int mt = 0; mt < 4; mt++)
#pragma unroll
                for (int nt = 0; nt < 4; nt++) mma16(acc[mt][nt], ah[mt], bh[nt]);
        };

        ISSUE(0);
        ISSUE(1);
#pragma unroll 1
        for (int ch = 0; ch < 32; ch++) {
            if (ch == 31) { CP_WAIT0(); } else { CP_WAIT1(); }
            __syncthreads();
            if (ch < 30) ISSUE(ch + 2);
            COMP(ch);
        }
        __syncthreads();

        {
            const int rb = m0 + wm + (lane >> 2);
            const int cb = n0 + wn + 2 * (lane & 3);
            __half* Oz = OUT + zoff;
#pragma unroll
            for (int mt = 0; mt < 4; mt++) {
                int r0 = rb + mt * 16, r1 = r0 + 8;
                float g0 = gamma[r0], g1 = gamma[r1];
                float e0 = beta[r0],  e1 = beta[r1];
#pragma unroll
                for (int nt = 0; nt < 4; nt++) {
                    int cc = cb + nt * 8;
                    float* c = acc[mt][nt];
                    float* vcell = &Vst[((mt * 4 + nt) * 4) * 256 + tid];
                    float y0 = __fmul_rn(c[0], WSCALE_INV);
                    float y1 = __fmul_rn(c[1], WSCALE_INV);
                    float y2 = __fmul_rn(c[2], WSCALE_INV);
                    float y3 = __fmul_rn(c[3], WSCALE_INV);
                    y0 = __fadd_rn(__fmul_rn(__fmul_rn(g0, y0), inv), e0);
                    y1 = __fadd_rn(__fmul_rn(__fmul_rn(g0, y1), inv), e0);
                    y2 = __fadd_rn(__fmul_rn(__fmul_rn(g1, y2), inv), e1);
                    y3 = __fadd_rn(__fmul_rn(__fmul_rn(g1, y3), inv), e1);
                    float vv0 = vcell[0], vv1 = vcell[256];
                    float vv2 = vcell[512], vv3 = vcell[768];
                    float s0 = lif_step(vv0, y0, 1.0f);
                    float s1 = lif_step(vv1, y1, 1.0f);
                    float s2 = lif_step(vv2, y2, 1.0f);
                    float s3 = lif_step(vv3, y3, 1.0f);
                    vcell[0] = vv0; vcell[256] = vv1;
                    vcell[512] = vv2; vcell[768] = vv3;
                    *(uint32_t*)(Oz + (size_t)r0 * N_ + cc) =
                        packh(__float2half_rn(s0), __float2half_rn(s1));
                    *(uint32_t*)(Oz + (size_t)r1 * N_ + cc) =
                        packh(__float2half_rn(s2), __float2half_rn(s3));
                }
            }
        }
    }
}

// ============================================================================
// Projection GEMM + BN, K-chunk 32, 3-stage cp.async (R16-proven, unchanged).
// ============================================================================
__global__ __launch_bounds__(256, 2) void gemm_bn_p32(
    float* __restrict__ OUT,
    const float* __restrict__ gamma, const float* __restrict__ beta,
    const float* __restrict__ bias, float inv)
{
    extern __shared__ char smbuf[];
    const uint32_t sbase = smem_u32(smbuf);

    const __half* Whi = g_whi + (size_t)3 * C_ * C_;
    const __half* Wlo = g_wlo + (size_t)3 * C_ * C_;
    const int z  = blockIdx.z;
    const int m0 = blockIdx.y * 128;
    const int n0 = blockIdx.x * 128;

    const int tid  = threadIdx.x;
    const int lane = tid & 31;
    const int wid  = tid >> 5;
    const int wm   = (wid >> 2) * 64;
    const int wn   = (wid & 3) * 32;

    const int mA  = tid >> 1;
    const int kh8 = tid & 1;
    const __half* WhiRow = Whi + (size_t)(m0 + mA) * C_ + kh8 * 8;
    const __half* WloRow = Wlo + (size_t)(m0 + mA) * C_ + kh8 * 8;
    const uint32_t abyte = (uint32_t)((mA * 2 + (kh8 ^ ((mA >> 2) & 1))) * 16);
    const int kB  = tid >> 4;
    const int seg = tid & 15;
    const uint32_t bbyte = (uint32_t)(kB * 256 + ((seg ^ (kB & 7))) * 16);

    const size_t zoff = (size_t)z * CN;
    const __half* BBase = gh_a + zoff + (size_t)kB * N_ + n0 + seg * 8;

    const int mrel = (lane & 7) | (((lane >> 3) & 1) << 3);
    const int hA   = (lane >> 4) & 1;
    uint32_t offA[4];
#pragma unroll
    for (int mt = 0; mt < 4; mt++) {
        int m = wm + mt * 16 + mrel;
        offA[mt] = (uint32_t)((m * 2 + (hA ^ ((m >> 2) & 1))) * 16);
    }
    const int krel = (lane & 7) | (((lane >> 3) & 1) << 3);
    const int nrel = ((lane >> 4) & 1) * 8;
    uint32_t offB[2];
#pragma unroll
    for (int p = 0; p < 2; p++) {
        int n = wn + p * 16 + nrel;
        offB[p] = (uint32_t)(krel * 256 + (((n >> 3) ^ (krel & 7))) * 16);
    }

    float acc[4][4][4];
#pragma unroll
    for (int i = 0; i < 4; i++)
#pragma unroll
        for (int j = 0; j < 4; j++)
#pragma unroll
            for (int e = 0; e < 4; e++) acc[i][j][e] = 0.0f;

    auto ISSUE = [&](int ch) {
        const uint32_t st = (uint32_t)(ch % 3) * 24576u;
        const int kb = ch * 32;
#pragma unroll
        for (int j = 0; j < 2; j++) {
            cp16(sbase + st + j * 4096 + abyte,          WhiRow + kb + j * 16);
            cp16(sbase + st + 8192 + j * 4096 + abyte,   WloRow + kb + j * 16);
            cp16(sbase + st + 16384 + j * 4096 + bbyte,  BBase + (size_t)(kb + j * 16) * N_);
        }
        CP_COMMIT();
    };

    auto COMP = [&](int ch) {
        const uint32_t st = (uint32_t)(ch % 3) * 24576u;
#pragma unroll
        for (int j = 0; j < 2; j++) {
            const uint32_t aHi = sbase + st + j * 4096;
            const uint32_t aLo = sbase + st + 8192 + j * 4096;
            const uint32_t bHi = sbase + st + 16384 + j * 4096;

            uint32_t ah[4][4], bh[4][2];
#pragma unroll
            for (int mt = 0; mt < 4; mt++) ldmx4(ah[mt], aHi + offA[mt]);
#pragma unroll
            for (int p = 0; p < 2; p++) {
                uint32_t tr[4];
                ldmx4t(tr, bHi + offB[p]);
                bh[2 * p][0] = tr[0]; bh[2 * p][1] = tr[1];
                bh[2 * p + 1][0] = tr[2]; bh[2 * p + 1][1] = tr[3];
            }
#pragma unroll
            for (int mt = 0; mt < 4; mt++)
#pragma unroll
                for (int nt = 0; nt < 4; nt++) mma16(acc[mt][nt], ah[mt], bh[nt]);
#pragma unroll
            for (int mt = 0; mt < 4; mt++) ldmx4(ah[mt], aLo + offA[mt]);
#pragma unroll
            for (int mt = 0; mt < 4; mt++)
#pragma unroll
                for (int nt = 0; nt < 4; nt++) mma16(acc[mt][nt], ah[mt], bh[nt]);
        }
    };

    ISSUE(0);
    ISSUE(1);
#pragma unroll 1
    for (int ch = 0; ch < 16; ch++) {
        if (ch == 15) { CP_WAIT0(); } else { CP_WAIT1(); }
        __syncthreads();
        if (ch < 14) ISSUE(ch + 2);
        COMP(ch);
    }

    {
        const int rb = m0 + wm + (lane >> 2);
        const int cb = n0 + wn + 2 * (lane & 3);
        float* Oz = OUT + zoff;
#pragma unroll
        for (int mt = 0; mt < 4; mt++) {
            int r0 = rb + mt * 16, r1 = r0 + 8;
            float g0 = gamma[r0], g1 = gamma[r1];
            float e0 = beta[r0],  e1 = beta[r1];
            float b0 = bias[r0],  b1 = bias[r1];
#pragma unroll
            for (int nt = 0; nt < 4; nt++) {
                int cc = cb + nt * 8;
                float* c = acc[mt][nt];
                float y0 = __fadd_rn(__fmul_rn(c[0], WSCALE_INV), b0);
                float y1 = __fadd_rn(__fmul_rn(c[1], WSCALE_INV), b0);
                float y2 = __fadd_rn(__fmul_rn(c[2], WSCALE_INV), b1);
                float y3 = __fadd_rn(__fmul_rn(c[3], WSCALE_INV), b1);
                y0 = __fadd_rn(__fmul_rn(__fmul_rn(g0, y0), inv), e0);
                y1 = __fadd_rn(__fmul_rn(__fmul_rn(g0, y1), inv), e0);
                y2 = __fadd_rn(__fmul_rn(__fmul_rn(g1, y2), inv), e1);
                y3 = __fadd_rn(__fmul_rn(__fmul_rn(g1, y3), inv), e1);
                *(float2*)(Oz + (size_t)r0 * N_ + cc) = make_float2(y0, y1);
                *(float2*)(Oz + (size_t)r1 * N_ + cc) = make_float2(y2, y3);
            }
        }
    }
}

// ============================================================================
// Multi-step LIF, float4-vectorized (same per-element op order -> identical)
// ============================================================================
__global__ void lif_kernel4(const float* __restrict__ in, float* __restrict__ out, float thr)
{
    size_t i4 = (size_t)blockIdx.x * blockDim.x + threadIdx.x;   // 0 .. PER_T/4-1
    float4 v = make_float4(0.0f, 0.0f, 0.0f, 0.0f);
#pragma unroll
    for (int t = 0; t < T_; t++) {
        float4 x = *(const float4*)(in + (size_t)t * PER_T + i4 * 4);
        float4 s;
        s.x = lif_step(v.x, x.x, thr);
        s.y = lif_step(v.y, x.y, thr);
        s.z = lif_step(v.z, x.z, thr);
        s.w = lif_step(v.w, x.w, thr);
        *(float4*)(out + (size_t)t * PER_T + i4 * 4) = s;
    }
}

// ============================================================================
// kv via tensor cores, 2-stage cp.async (R14-proven, unchanged)
// ============================================================================
__global__ __launch_bounds__(256) void kv_mma()
{
    extern __shared__ char smem[];
    const uint32_t sb = smem_u32(smem);

    const int tbh = blockIdx.x;
    const int tb = tbh >> 3, h = tbh & 7;
    const __half* K = gh_k + (size_t)tb * CN + (size_t)h * 64 * N_;
    const __half* V = gh_v + (size_t)tb * CN + (size_t)h * 64 * N_;

    const int tid = threadIdx.x;
    const int lane = tid & 31;
    const int w = tid >> 5;
    const int mt = (w & 3) * 16;
    const int nh = (w >> 2) * 32;

    float acc[4][4];
#pragma unroll
    for (int i = 0; i < 4; i++)
#pragma unroll
        for (int j = 0; j < 4; j++) acc[i][j] = 0.0f;

    const __half* src = (tid < 128) ? K : V;
    const uint32_t mofs = (tid < 128) ? 0u : 16384u;
    const int lt = tid & 127;

    auto ISSUE = [&](int c) {
        const uint32_t st = (uint32_t)(c & 1) * 32768u;
#pragma unroll
        for (int i = 0; i < 8; i++) {
            int idx = lt + i * 128;
            int row = idx >> 4, seg = idx & 15;
            int phys = seg ^ (row & 7);
            cp16(sb + st + mofs + (uint32_t)(row * 256 + phys * 16),
                 src + (size_t)row * N_ + c * 128 + seg * 8);
        }
        CP_COMMIT();
    };

    ISSUE(0);
#pragma unroll 1
    for (int c = 0; c < 8; c++) {
        CP_WAIT0();
        __syncthreads();
        if (c < 7) ISSUE(c + 1);

        const uint32_t skb = sb + (uint32_t)(c & 1) * 32768u;
        const uint32_t svb = skb + 16384u;
#pragma unroll
        for (int j = 0; j < 8; j++) {
            uint32_t a[4];
            {
                int row = mt + (lane & 7) + ((lane >> 3) & 1) * 8;
                int seg = 2 * j + (lane >> 4);
                ldmx4(a, skb + row * 256 + (seg ^ (row & 7)) * 16);
            }
#pragma unroll
            for (int p = 0; p < 2; p++) {
                uint32_t r[4];
                int row = nh + p * 16 + (lane & 7) + ((lane >> 4) & 1) * 8;
                int seg = 2 * j + ((lane >> 3) & 1);
                ldmx4(r, svb + row * 256 + (seg ^ (row & 7)) * 16);
                mma16(acc[2 * p],     a, &r[0]);
                mma16(acc[2 * p + 1], a, &r[2]);
            }
        }
    }

    __half* out = g_kvh + (size_t)tbh * 4096;
    const int d0 = mt + (lane >> 2);
    const int eb = nh + 2 * (lane & 3);
#pragma unroll
    for (int nt = 0; nt < 4; nt++) {
        int e = eb + nt * 8;
        out[(size_t)e * 64 + d0]           = __float2half_rn(acc[nt][0]);
        out[(size_t)(e + 1) * 64 + d0]     = __float2half_rn(acc[nt][1]);
        out[(size_t)e * 64 + d0 + 8]       = __float2half_rn(acc[nt][2]);
        out[(size_t)(e + 1) * 64 + d0 + 8] = __float2half_rn(acc[nt][3]);
    }
}

// ============================================================================
// av via tensor cores + fused attn-LIF, 2-stage cp.async (R16-proven)
// ============================================================================
__global__ __launch_bounds__(256, 2) void av_lif_mma()
{
    extern __shared__ char smem[];
    const uint32_t sb = smem_u32(smem);

    const int bh = blockIdx.y;
    const int b = bh >> 3, h = bh & 7;
    const int n0 = blockIdx.x * 128;

    const int tid = threadIdx.x;
    const int lane = tid & 31;
    const int w = tid >> 5;

    const int mrel = (lane & 7) + ((lane >> 3) & 1) * 8;
    const int hA = (lane >> 4) & 1;
    const int krel = (lane & 7) | (((lane >> 3) & 1) << 3);
    const int nrel = ((lane >> 4) & 1) * 8;
    const int nseg = (w * 16 + nrel) >> 3;

    float vst[4][2][4];
#pragma unroll
    for (int i = 0; i < 4; i++)
#pragma unroll
        for (int j = 0; j < 2; j++)
#pragma unroll
            for (int e = 0; e < 4; e++) vst[i][j][e] = 0.0f;

    auto ISSUE = [&](int t) {
        const int tb = t * 8 + b;
        const __half* KV = g_kvh + ((size_t)tb * 8 + h) * 4096;
        const __half* Q  = gh_q + (size_t)tb * CN + (size_t)h * 64 * N_;
        const uint32_t st = (uint32_t)(t & 1) * 40960u;
#pragma unroll
        for (int i = 0; i < 2; i++) {
            int idx = tid + i * 256;
            int e = idx >> 3, seg = idx & 7;
            int phys = seg ^ (e & 7);
            cp16(sb + st + (uint32_t)(e * 128 + phys * 16),
                 KV + (size_t)e * 64 + seg * 8);
        }
#pragma unroll
        for (int i = 0; i < 4; i++) {
            int idx = tid + i * 256;
            int d = idx >> 4, seg = idx & 15;
            int phys = seg ^ (d & 7);
            cp16(sb + st + 8192u + (uint32_t)(d * 256 + phys * 16),
                 Q + (size_t)d * N_ + n0 + seg * 8);
        }
        CP_COMMIT();
    };

    ISSUE(0);
#pragma unroll 1
    for (int t = 0; t < 4; t++) {
        CP_WAIT0();
        __syncthreads();
        if (t < 3) ISSUE(t + 1);

        const uint32_t sab = sb + (uint32_t)(t & 1) * 40960u;
        const uint32_t sqb = sab + 8192u;

        float acc[4][2][4];
#pragma unroll
        for (int i = 0; i < 4; i++)
#pragma unroll
            for (int j = 0; j < 2; j++)
#pragma unroll
                for (int e = 0; e < 4; e++) acc[i][j][e] = 0.0f;

#pragma unroll
        for (int j = 0; j < 4; j++) {
            uint32_t bq[2][2];
            {
                uint32_t tr[4];
                int kr = j * 16 + krel;
                ldmx4t(tr, sqb + kr * 256 + ((nseg ^ (kr & 7))) * 16);
                bq[0][0] = tr[0]; bq[0][1] = tr[1];
                bq[1][0] = tr[2]; bq[1][1] = tr[3];
            }
#pragma unroll
            for (int mt = 0; mt < 4; mt++) {
                uint32_t a[4];
                int row = mt * 16 + mrel;
                int seg = 2 * j + hA;
                ldmx4(a, sab + row * 128 + ((seg ^ (row & 7))) * 16);
                mma16(acc[mt][0], a, bq[0]);
                mma16(acc[mt][1], a, bq[1]);
            }
        }

        const int tb = t * 8 + b;
        __half* A = gh_a + (size_t)tb * CN + (size_t)h * 64 * N_;
        const int cb = n0 + w * 16 + 2 * (lane & 3);
#pragma unroll
        for (int mt = 0; mt < 4; mt++) {
            int e0 = mt * 16 + (lane >> 2), e1 = e0 + 8;
#pragma unroll
            for (int nt = 0; nt < 2; nt++) {
                int cc = cb + nt * 8;
                float* c = acc[mt][nt];
                float* vv = vst[mt][nt];
                float s0 = lif_step(vv[0], __fmul_rn(c[0], 0.125f), 0.5f);
                float s1 = lif_step(vv[1], __fmul_rn(c[1], 0.125f), 0.5f);
                float s2 = lif_step(vv[2], __fmul_rn(c[2], 0.125f), 0.5f);
                float s3 = lif_step(vv[3], __fmul_rn(c[3], 0.125f), 0.5f);
                *(uint32_t*)(A + (size_t)e0 * N_ + cc) =
                    packh(__float2half_rn(s0), __float2half_rn(s1));
                *(uint32_t*)(A + (size_t)e1 * N_ + cc) =
                    packh(__float2half_rn(s2), __float2half_rn(s3));
            }
        }
    }
}

// ============================================================================
extern "C" void kernel_launch(void* const* d_in, const int* in_sizes, int n_in,
                              void* d_out, int out_size)
{
    const float* x   = (const float*)d_in[0];
    const float* Wq  = (const float*)d_in[1];
    const float* qg  = (const float*)d_in[2];
    const float* qb  = (const float*)d_in[3];
    const float* Wk  = (const float*)d_in[4];
    const float* kg  = (const float*)d_in[5];
    const float* kb  = (const float*)d_in[6];
    const float* Wv  = (const float*)d_in[7];
    const float* vg  = (const float*)d_in[8];
    const float* vb  = (const float*)d_in[9];
    const float* Wp  = (const float*)d_in[10];
    const float* bp  = (const float*)d_in[11];
    const float* pg  = (const float*)d_in[12];
    const float* pb  = (const float*)d_in[13];
    float* out = (float*)d_out;

    __half *hq, *hk, *hv;
    float* p;
    cudaGetSymbolAddress((void**)&hq, gh_q);
    cudaGetSymbolAddress((void**)&hk, gh_k);
    cudaGetSymbolAddress((void**)&hv, gh_v);
    cudaGetSymbolAddress((void**)&p, g_p);

    float one_eps = 1.0f + 1e-5f;
    float inv = (float)(1.0 / sqrt((double)one_eps));

    const int SMEM_QKV = 49152 + 65536;   // 114688 -> 2 CTA/SM (R15-proven)
    const int SMEM_KV  = 65536;
    const int SMEM_P   = 73728;           // 3 x 24KB -> 2 CTA/SM
    const int SMEM_AV  = 81920;           // 2 x 40KB -> 2 CTA/SM
    cudaFuncSetAttribute((const void*)gemm_lif_qkv,
                         cudaFuncAttributeMaxDynamicSharedMemorySize, SMEM_QKV);
    cudaFuncSetAttribute((const void*)kv_mma,
                         cudaFuncAttributeMaxDynamicSharedMemorySize, SMEM_KV);
    cudaFuncSetAttribute((const void*)gemm_bn_p32,
                         cudaFuncAttributeMaxDynamicSharedMemorySize, SMEM_P);
    cudaFuncSetAttribute((const void*)av_lif_mma,
                         cudaFuncAttributeMaxDynamicSharedMemorySize, SMEM_AV);

    // merged one-shot pre-splits (x + all 4 W matrices in one launch)
    split_all<<<XB_BLOCKS + WB_BLOCKS, 256>>>(x, Wq, Wk, Wv, Wp);

    // merged q/k/v: 768 identical CTAs in one scheduling pool
    gemm_lif_qkv<<<dim3(N_ / 128, C_ / 128, 24), 256, SMEM_QKV>>>(
        hq, hk, hv, qg, qb, kg, kb, vg, vb, inv);

    kv_mma<<<256, 256, SMEM_KV>>>();
    av_lif_mma<<<dim3(8, 64), 256, SMEM_AV>>>();

    // projection: K32 3-stage GEMM+BN (z=32), then vectorized LIF
    gemm_bn_p32<<<dim3(N_ / 128, C_ / 128, TB), 256, SMEM_P>>>(p, pg, pb, bp, inv);
    lif_kernel4<<<PER_T / 4 / 256, 256>>>(p, out, 1.0f);
}